// round 15
// baseline (speedup 1.0000x reference)
#include <cuda_runtime.h>
#include <cuda_bf16.h>
#include <cstdint>
#include <cmath>

#define B_ 4
#define T_ 4096
#define D_ 1024
#define H_ 16
#define HD_ 64
#define CAP_ 512
#define M_ 2048
#define DFF_ 2730
#define DFF2_ 5460          // 2*DFF (fused W1|W2 GEMM N)
#define LD12_ 5472          // row pitch of fused U12 output (mult of 32)
#define DFFP2_ 2752         // padded K for W3 GEMM (mult of 32)

// ---------------------------------------------------------------------------
// fp32 workspace
// ---------------------------------------------------------------------------
constexpr size_t OFF_SCORES = 0;
constexpr size_t OFF_XSEL   = OFF_SCORES + (size_t)B_ * T_;
constexpr size_t OFF_Y1     = OFF_XSEL   + (size_t)M_ * D_;
constexpr size_t WS_TOTAL   = OFF_Y1     + (size_t)M_ * D_;

__device__ __align__(256) float d_ws[WS_TOTAL];

// bf16 workspace
constexpr size_t HB_H    = 0;
constexpr size_t HB_QKV  = HB_H    + (size_t)M_ * D_;
constexpr size_t HB_ATTN = HB_QKV  + (size_t)M_ * 3 * D_;
constexpr size_t HB_H2   = HB_ATTN + (size_t)M_ * D_;
constexpr size_t HB_U12  = HB_H2   + (size_t)M_ * D_;
constexpr size_t HB_U    = HB_U12  + (size_t)M_ * LD12_;
constexpr size_t HB_W3P  = HB_U    + (size_t)M_ * DFFP2_;
constexpr size_t HB_WQKV = HB_W3P  + (size_t)D_ * DFFP2_;
constexpr size_t HB_WOUT = HB_WQKV + (size_t)3 * D_ * D_;
constexpr size_t HB_W12  = HB_WOUT + (size_t)D_ * D_;
constexpr size_t HB_TOTAL= HB_W12  + (size_t)DFF2_ * D_;

__device__ __align__(256) __nv_bfloat16 d_hb[HB_TOTAL];
__device__ int d_idx[M_];
__device__ unsigned long long d_keys[B_ * T_];

// ---------------------------------------------------------------------------
// helpers
// ---------------------------------------------------------------------------
__device__ __forceinline__ void cp_async16(uint32_t dst, const void* src, bool valid) {
    int sz = valid ? 16 : 0;
    asm volatile("cp.async.cg.shared.global [%0], [%1], 16, %2;\n"
                 :: "r"(dst), "l"(src), "r"(sz));
}
__device__ __forceinline__ void ldsm_x4(uint32_t* r, const void* p) {
    uint32_t a = (uint32_t)__cvta_generic_to_shared(p);
    asm volatile("ldmatrix.sync.aligned.m8n8.x4.shared.b16 {%0,%1,%2,%3}, [%4];"
                 : "=r"(r[0]), "=r"(r[1]), "=r"(r[2]), "=r"(r[3]) : "r"(a));
}
__device__ __forceinline__ void ldsm_x2(uint32_t* r, const void* p) {
    uint32_t a = (uint32_t)__cvta_generic_to_shared(p);
    asm volatile("ldmatrix.sync.aligned.m8n8.x2.shared.b16 {%0,%1}, [%2];"
                 : "=r"(r[0]), "=r"(r[1]) : "r"(a));
}
__device__ __forceinline__ void ldsm_x2t(uint32_t* r, const void* p) {
    uint32_t a = (uint32_t)__cvta_generic_to_shared(p);
    asm volatile("ldmatrix.sync.aligned.m8n8.x2.trans.shared.b16 {%0,%1}, [%2];"
                 : "=r"(r[0]), "=r"(r[1]) : "r"(a));
}
__device__ __forceinline__ void mma_bf16(float* c, const uint32_t* a, uint32_t b0, uint32_t b1) {
    asm volatile(
        "mma.sync.aligned.m16n8k16.row.col.f32.bf16.bf16.f32 "
        "{%0,%1,%2,%3}, {%4,%5,%6,%7}, {%8,%9}, {%0,%1,%2,%3};\n"
        : "+f"(c[0]), "+f"(c[1]), "+f"(c[2]), "+f"(c[3])
        : "r"(a[0]), "r"(a[1]), "r"(a[2]), "r"(a[3]), "r"(b0), "r"(b1));
}

// ---------------------------------------------------------------------------
// block reduce (256 threads)
// ---------------------------------------------------------------------------
__device__ __forceinline__ float block_reduce_sum_256(float v, float* red)
{
    #pragma unroll
    for (int o = 16; o; o >>= 1) v += __shfl_xor_sync(0xFFFFFFFFu, v, o);
    if ((threadIdx.x & 31) == 0) red[threadIdx.x >> 5] = v;
    __syncthreads();
    float tot = 0.f;
    #pragma unroll
    for (int w = 0; w < 8; w++) tot += red[w];
    return tot;
}

// ---------------------------------------------------------------------------
// Weight prep work item (range-dispatched)
// ---------------------------------------------------------------------------
constexpr size_t WP_N1 = (size_t)3 * D_ * D_ / 4;            // Wqkv float4s
constexpr size_t WP_N2 = WP_N1 + (size_t)D_ * D_ / 4;        // + Wout
constexpr size_t WP_N3 = WP_N2 + (size_t)DFF2_ * D_ / 4;     // + W12
constexpr size_t WP_N4 = WP_N3 + (size_t)D_ * DFFP2_ / 2;    // + W3 (pair idx)
constexpr size_t WP_SPLIT = 1927680;                          // = 256*7530, ~half

// out = x copy (float4 items), split between the two topk kernels
constexpr size_t CP_N     = (size_t)B_ * T_ * D_ / 4;        // 4194304 float4s
constexpr size_t CP_SPLIT = CP_N / 2;                        // 2097152 = 256*8192

__device__ __forceinline__ void weight_prep_item(size_t i,
                                                 const float* __restrict__ Wqkv,
                                                 const float* __restrict__ Wout,
                                                 const float* __restrict__ W1,
                                                 const float* __restrict__ W2,
                                                 const float* __restrict__ W3)
{
    if (i >= WP_N3) {
        size_t j = i - WP_N3;
        int n = (int)(j / (DFFP2_ / 2));
        int k2 = (int)(j - (size_t)n * (DFFP2_ / 2)) * 2;
        __nv_bfloat162 r;
        if (k2 < DFF_) {
            float2 v = *(const float2*)(W3 + (size_t)n * DFF_ + k2);
            r = __floats2bfloat162_rn(v.x, v.y);
        } else {
            r = __floats2bfloat162_rn(0.f, 0.f);
        }
        *(__nv_bfloat162*)(d_hb + HB_W3P + (size_t)n * DFFP2_ + k2) = r;
        return;
    }
    const float* src;
    __nv_bfloat162* dst;
    if (i < WP_N1) {
        src = (const float*)((const float4*)Wqkv + i);
        dst = (__nv_bfloat162*)(d_hb + HB_WQKV) + i * 2;
    } else if (i < WP_N2) {
        size_t j = i - WP_N1;
        src = (const float*)((const float4*)Wout + j);
        dst = (__nv_bfloat162*)(d_hb + HB_WOUT) + j * 2;
    } else {
        size_t j = i - WP_N2;
        int row = (int)(j >> 8);                // D_/4 = 256
        int c4  = (int)(j & 255);
        const float* s = (row < DFF_) ? (W1 + (size_t)row * D_)
                                      : (W2 + (size_t)(row - DFF_) * D_);
        src = s + c4 * 4;
        dst = (__nv_bfloat162*)(d_hb + HB_W12 + (size_t)row * D_ + c4 * 4);
    }
    float4 v = *(const float4*)src;
    dst[0] = __floats2bfloat162_rn(v.x, v.y);
    dst[1] = __floats2bfloat162_rn(v.z, v.w);
}

// ---------------------------------------------------------------------------
// 1. Router only (dot products; the out=x copy rides in the topk kernels)
// ---------------------------------------------------------------------------
__global__ __launch_bounds__(256) void router_kernel(const float* __restrict__ x,
                                                     const float* __restrict__ wr)
{
    __shared__ float red[4][8];
    int tok0 = blockIdx.x * 4;
    int tid = threadIdx.x;
    float4 w = ((const float4*)wr)[tid];

    float4 v[4];
    #pragma unroll
    for (int t = 0; t < 4; t++)
        v[t] = ((const float4*)(x + (size_t)(tok0 + t) * D_))[tid];

    #pragma unroll
    for (int t = 0; t < 4; t++) {
        float dot = v[t].x * w.x + v[t].y * w.y + v[t].z * w.z + v[t].w * w.w;
        #pragma unroll
        for (int o = 16; o; o >>= 1) dot += __shfl_xor_sync(0xFFFFFFFFu, dot, o);
        if ((tid & 31) == 0) red[t][tid >> 5] = dot;
    }
    __syncthreads();
    if (tid < 4) {
        float s = 0.f;
        #pragma unroll
        for (int wv = 0; wv < 8; wv++) s += red[tid][wv];
        d_ws[OFF_SCORES + tok0 + tid] = s;
    }
}

// ---------------------------------------------------------------------------
// 2a. Top-k chunk sort (blocks 0-31) + weight-prep half 1 + copy half 1
// ---------------------------------------------------------------------------
constexpr int SORT_PREP_BLKS = (int)(WP_SPLIT / 256);          // 7530
constexpr int SORT_COPY_BLKS = (int)(CP_SPLIT / 256);          // 8192

__global__ __launch_bounds__(256) void topk_sort_prep_kernel(const float* __restrict__ Wqkv,
                                                             const float* __restrict__ Wout,
                                                             const float* __restrict__ W1,
                                                             const float* __restrict__ W2,
                                                             const float* __restrict__ W3,
                                                             const float* __restrict__ x,
                                                             float* __restrict__ out)
{
    __shared__ unsigned long long key[512];

    if (blockIdx.x >= 32) {
        int bi = blockIdx.x - 32;
        if (bi < SORT_PREP_BLKS) {
            size_t i = (size_t)bi * 256 + threadIdx.x;
            weight_prep_item(i, Wqkv, Wout, W1, W2, W3);
        } else {
            size_t i = (size_t)(bi - SORT_PREP_BLKS) * 256 + threadIdx.x;
            if (i < CP_SPLIT)
                ((float4*)out)[i] = ((const float4*)x)[i];
        }
        return;
    }

    int chunk = blockIdx.x;
    int b = chunk >> 3;
    int c0 = (chunk & 7) * 512;

    for (int t = threadIdx.x; t < 512; t += 256) {
        int gi = c0 + t;
        float s = d_ws[OFF_SCORES + (size_t)b * T_ + gi];
        unsigned int u = __float_as_uint(s);
        u = (u & 0x80000000u) ? ~u : (u | 0x80000000u);
        key[t] = ((unsigned long long)u << 32) | (unsigned int)(0xFFFFFFFFu - (unsigned)gi);
    }
    __syncthreads();
    for (int k = 2; k <= 512; k <<= 1) {
        for (int j = k >> 1; j > 0; j >>= 1) {
            for (int t = threadIdx.x; t < 512; t += 256) {
                int l = t ^ j;
                if (l > t) {
                    unsigned long long a = key[t], c = key[l];
                    bool desc = ((t & k) == 0);
                    if (desc ? (a < c) : (a > c)) { key[t] = c; key[l] = a; }
                }
            }
            __syncthreads();
        }
    }
    for (int t = threadIdx.x; t < 512; t += 256)
        d_keys[(size_t)b * T_ + c0 + t] = key[t];
}

// ---------------------------------------------------------------------------
// 2b. Top-k merge (blocks 0-3) + weight-prep half 2 + copy half 2
// ---------------------------------------------------------------------------
constexpr int MERGE_PREP_BLKS = (int)((WP_N4 - WP_SPLIT + 511) / 512);   // 3765
constexpr int MERGE_COPY_BLKS = (int)((CP_N - CP_SPLIT) / 512);          // 4096

__global__ __launch_bounds__(512) void topk_merge_prep_kernel(const float* __restrict__ Wqkv,
                                                              const float* __restrict__ Wout,
                                                              const float* __restrict__ W1,
                                                              const float* __restrict__ W2,
                                                              const float* __restrict__ W3,
                                                              const float* __restrict__ x,
                                                              float* __restrict__ out)
{
    __shared__ unsigned long long key[T_];

    if (blockIdx.x >= B_) {
        int bi = blockIdx.x - B_;
        if (bi < MERGE_PREP_BLKS) {
            size_t i = WP_SPLIT + (size_t)bi * 512 + threadIdx.x;
            if (i < WP_N4)
                weight_prep_item(i, Wqkv, Wout, W1, W2, W3);
        } else {
            size_t i = CP_SPLIT + (size_t)(bi - MERGE_PREP_BLKS) * 512 + threadIdx.x;
            if (i < CP_N)
                ((float4*)out)[i] = ((const float4*)x)[i];
        }
        return;
    }

    int b = blockIdx.x;
    for (int t = threadIdx.x; t < T_; t += 512)
        key[t] = d_keys[(size_t)b * T_ + t];
    __syncthreads();

    #pragma unroll
    for (int r = 0; r < 3; r++) {
        int pairs = 4 >> r;
        int stride = 1024 << r;
        int half = 512 << r;
        for (int e = threadIdx.x; e < pairs * 512; e += 512) {
            int p = e >> 9, i = e & 511;
            int base = p * stride;
            unsigned long long a = key[base + i];
            unsigned long long bb = key[base + half + 511 - i];
            if (bb > a) key[base + i] = bb;
        }
        __syncthreads();
        for (int j = 256; j > 0; j >>= 1) {
            for (int e = threadIdx.x; e < pairs * 256; e += 512) {
                int p = e >> 8, q = e & 255;
                int i = ((q & ~(j - 1)) << 1) | (q & (j - 1));
                int base = p * stride;
                unsigned long long a = key[base + i], c = key[base + i + j];
                if (a < c) { key[base + i] = c; key[base + i + j] = a; }
            }
            __syncthreads();
        }
    }
    for (int t = threadIdx.x; t < CAP_; t += 512)
        d_idx[b * CAP_ + t] = (int)(0xFFFFFFFFu - (unsigned int)(key[t] & 0xFFFFFFFFu));
}

// ---------------------------------------------------------------------------
// 3. Gather + RMSNorm (writes XSEL fp32 + H bf16)
// ---------------------------------------------------------------------------
__global__ __launch_bounds__(256) void gather_rmsnorm_kernel(const float* __restrict__ x,
                                                             const float* __restrict__ g)
{
    __shared__ float red[8];
    int row = blockIdx.x;
    int b = row >> 9;
    int t = d_idx[row];
    int tid = threadIdx.x;
    float4 v = ((const float4*)(x + ((size_t)b * T_ + t) * D_))[tid];
    float ss = v.x*v.x + v.y*v.y + v.z*v.z + v.w*v.w;
    float tot = block_reduce_sum_256(ss, red);
    float rinv = rsqrtf(tot * (1.f / D_) + 1e-6f);
    float4 gv = ((const float4*)g)[tid];
    ((float4*)(d_ws + OFF_XSEL + (size_t)row * D_))[tid] = v;
    __nv_bfloat162* hb = (__nv_bfloat162*)(d_hb + HB_H + (size_t)row * D_);
    hb[tid * 2]     = __floats2bfloat162_rn(v.x * rinv * gv.x, v.y * rinv * gv.y);
    hb[tid * 2 + 1] = __floats2bfloat162_rn(v.z * rinv * gv.z, v.w * rinv * gv.w);
}

// ---------------------------------------------------------------------------
// 4. RMSNorm y1 -> H2b
// ---------------------------------------------------------------------------
__global__ __launch_bounds__(256) void rmsnorm2_kernel(const float* __restrict__ g)
{
    __shared__ float red[8];
    int row = blockIdx.x;
    int tid = threadIdx.x;
    float4 v = ((const float4*)(d_ws + OFF_Y1 + (size_t)row * D_))[tid];
    float ss = v.x*v.x + v.y*v.y + v.z*v.z + v.w*v.w;
    float tot = block_reduce_sum_256(ss, red);
    float rinv = rsqrtf(tot * (1.f / D_) + 1e-6f);
    float4 gv = ((const float4*)g)[tid];
    __nv_bfloat162* hb = (__nv_bfloat162*)(d_hb + HB_H2 + (size_t)row * D_);
    hb[tid * 2]     = __floats2bfloat162_rn(v.x * rinv * gv.x, v.y * rinv * gv.y);
    hb[tid * 2 + 1] = __floats2bfloat162_rn(v.z * rinv * gv.z, v.w * rinv * gv.w);
}

// ---------------------------------------------------------------------------
// 5. BF16 mma.sync GEMM (NT) — round-9 exact mainloop.
//    mode 0: fp32 out (+ADD linear rows). mode 1: bf16 out.
//    mode 3: fp32 out, rows scattered to out via d_idx, ADD linear.
// ---------------------------------------------------------------------------
#define GBK2 32
#define BPITCH 40
#define G_NST 3
constexpr int G_STAGE_HALVES = 2 * 128 * BPITCH;
constexpr int G_SMEM_BYTES   = G_NST * G_STAGE_HALVES * 2;   // 61440

__global__ __launch_bounds__(256, 2) void bf16_gemm_nt(const __nv_bfloat16* __restrict__ A,
                                                       const __nv_bfloat16* __restrict__ Bw,
                                                       void* __restrict__ Cv,
                                                       const float* __restrict__ ADD,
                                                       int M, int N, int K, int ldc,
                                                       int mode)
{
    extern __shared__ __nv_bfloat16 gs[];

    const int tid  = threadIdx.x;
    const int lane = tid & 31, warp = tid >> 5;
    const int g    = lane >> 2, tg = lane & 3;
    const int wm   = warp >> 2;
    const int wn   = warp & 3;
    const int row0 = blockIdx.y * 128;
    const int col0 = blockIdx.x * 128;
    const int nk   = K / GBK2;

    float acc[4][4][4];
    #pragma unroll
    for (int i = 0; i < 4; i++)
        #pragma unroll
        for (int j = 0; j < 4; j++)
            #pragma unroll
            for (int r = 0; r < 4; r++) acc[i][j][r] = 0.f;

    auto issue = [&](int s, int ki) {
        __nv_bfloat16* As = gs + s * G_STAGE_HALVES;
        __nv_bfloat16* Bs = As + 128 * BPITCH;
        int k0 = ki * GBK2;
        #pragma unroll
        for (int i = 0; i < 2; i++) {
            int c = tid + 256 * i;
            int r = c >> 2, off = (c & 3) * 8;
            cp_async16((uint32_t)__cvta_generic_to_shared(&As[r * BPITCH + off]),
                       A + (size_t)(row0 + r) * K + k0 + off, true);
            cp_async16((uint32_t)__cvta_generic_to_shared(&Bs[r * BPITCH + off]),
                       Bw + (size_t)(col0 + r) * K + k0 + off, (col0 + r) < N);
        }
        asm volatile("cp.async.commit_group;\n");
    };

    issue(0, 0);
    issue(1, 1);
    issue(2, 2);

    for (int i = 0; i < nk; i++) {
        int s = i - (i / G_NST) * G_NST;
        int issued = (i + G_NST < nk) ? (i + G_NST) : nk;
        int pend = issued - i - 1;
        if (pend >= 2)      asm volatile("cp.async.wait_group 2;\n");
        else if (pend == 1) asm volatile("cp.async.wait_group 1;\n");
        else                asm volatile("cp.async.wait_group 0;\n");
        __syncthreads();

        const __nv_bfloat16* As = gs + s * G_STAGE_HALVES;
        const __nv_bfloat16* Bs = As + 128 * BPITCH;

        #pragma unroll
        for (int kk = 0; kk < GBK2; kk += 16) {
            uint32_t af[4][4];
            #pragma unroll
            for (int mt = 0; mt < 4; mt++)
                ldsm_x4(af[mt], &As[(wm * 64 + mt * 16 + (lane & 15)) * BPITCH
                                    + kk + ((lane >> 4) << 3)]);
            #pragma unroll
            for (int pb = 0; pb < 2; pb++) {
                uint32_t bq[4];
                ldsm_x4(bq, &Bs[(wn * 32 + pb * 16 + (lane & 7) + ((lane >> 3) & 1) * 8) * BPITCH
                                + kk + ((lane >> 4) << 3)]);
                #pragma unroll
                for (int mt = 0; mt < 4; mt++) {
                    mma_bf16(acc[mt][pb * 2],     af[mt], bq[0], bq[2]);
                    mma_bf16(acc[mt][pb * 2 + 1], af[mt], bq[1], bq[3]);
                }
            }
        }
        __syncthreads();

        if (i + G_NST < nk) issue(s, i + G_NST);
    }

    #pragma unroll
    for (int mt = 0; mt < 4; mt++) {
        int r1 = row0 + wm * 64 + mt * 16 + g;
        int r2 = r1 + 8;
        size_t or1 = (size_t)r1, or2 = (size_t)r2;
        if (mode == 3) {
            or1 = (size_t)((r1 >> 9) * T_ + d_idx[r1]);
            or2 = (size_t)((r2 >> 9) * T_ + d_idx[r2]);
        }
        #pragma unroll
        for (int nt = 0; nt < 4; nt++) {
            int c = col0 + wn * 32 + nt * 8 + 2 * tg;
            if (c < N) {
                float2 v0 = make_float2(acc[mt][nt][0], acc[mt][nt][1]);
                float2 v1 = make_float2(acc[mt][nt][2], acc[mt][nt][3]);
                if (ADD) {
                    float2 a0 = *(const float2*)&ADD[(size_t)r1 * ldc + c];
                    float2 a1 = *(const float2*)&ADD[(size_t)r2 * ldc + c];
                    v0.x += a0.x; v0.y += a0.y;
                    v1.x += a1.x; v1.y += a1.y;
                }
                if (mode == 1) {
                    __nv_bfloat16* C = (__nv_bfloat16*)Cv;
                    *(__nv_bfloat162*)&C[(size_t)r1 * ldc + c] = __floats2bfloat162_rn(v0.x, v0.y);
                    *(__nv_bfloat162*)&C[(size_t)r2 * ldc + c] = __floats2bfloat162_rn(v1.x, v1.y);
                } else {
                    float* C = (float*)Cv;
                    *(float2*)&C[or1 * ldc + c] = v0;
                    *(float2*)&C[or2 * ldc + c] = v1;
                }
            }
        }
    }
}

// ---------------------------------------------------------------------------
// 6. Fused flash attention (bf16 mma.sync, validated round 4)
// ---------------------------------------------------------------------------
#define AP 72
#define SP 68
constexpr int FA_SMEM_BYTES = (4 * 64 * AP) * 2 + (64 * SP + 3 * 64) * 4;

__global__ __launch_bounds__(128) void flash_attn_kernel()
{
    extern __shared__ char fsm_raw[];
    __nv_bfloat16* Qs = (__nv_bfloat16*)fsm_raw;
    __nv_bfloat16* Ks = Qs + 64 * AP;
    __nv_bfloat16* Vs = Ks + 64 * AP;
    __nv_bfloat16* Pb = Vs + 64 * AP;
    float* Sf   = (float*)(Pb + 64 * AP);
    float* smM  = Sf + 64 * SP;
    float* smL  = smM + 64;
    float* smSc = smL + 64;

    const int bh = blockIdx.x;
    const int it = 7 - blockIdx.y;
    const int b  = bh >> 4, h = bh & 15;
    const int tid = threadIdx.x;
    const int lane = tid & 31, w = tid >> 5;
    const int g = lane >> 2, tg = lane & 3;
    const int m0 = w * 16;

    const __nv_bfloat16* qkv = d_hb + HB_QKV;
    const int tokQ0 = b * CAP_ + it * 64;

    #pragma unroll
    for (int i = 0; i < 4; i++) {
        int c = tid + 128 * i;
        int r = c >> 3, off = (c & 7) * 8;
        cp_async16((uint32_t)__cvta_generic_to_shared(&Qs[r * AP + off]),
                   qkv + (size_t)(tokQ0 + r) * (3 * D_) + h * 64 + off, true);
    }
    asm volatile("cp.async.commit_group;\n");

    if (tid < 64) { smM[tid] = -1e30f; smL[tid] = 0.f; }

    float acc[8][4];
    #pragma unroll
    for (int nt = 0; nt < 8; nt++)
        #pragma unroll
        for (int r = 0; r < 4; r++) acc[nt][r] = 0.f;

    for (int jt = 0; jt <= it; jt++) {
        const int tokK0 = b * CAP_ + jt * 64;
        #pragma unroll
        for (int i = 0; i < 4; i++) {
            int c = tid + 128 * i;
            int r = c >> 3, off = (c & 7) * 8;
            cp_async16((uint32_t)__cvta_generic_to_shared(&Ks[r * AP + off]),
                       qkv + (size_t)(tokK0 + r) * (3 * D_) + D_ + h * 64 + off, true);
            cp_async16((uint32_t)__cvta_generic_to_shared(&Vs[r * AP + off]),
                       qkv + (size_t)(tokK0 + r) * (3 * D_) + 2 * D_ + h * 64 + off, true);
        }
        asm volatile("cp.async.commit_group;\n");
        asm volatile("cp.async.wait_group 0;\n");
        __syncthreads();

        float sacc[8][4];
        #pragma unroll
        for (int nt = 0; nt < 8; nt++)
            #pragma unroll
            for (int r = 0; r < 4; r++) sacc[nt][r] = 0.f;

        #pragma unroll
        for (int kk = 0; kk < 64; kk += 16) {
            uint32_t a[4];
            ldsm_x4(a, &Qs[(m0 + (lane & 15)) * AP + kk + ((lane >> 4) << 3)]);
            #pragma unroll
            for (int nt = 0; nt < 8; nt++) {
                uint32_t bb[2];
                ldsm_x2(bb, &Ks[(nt * 8 + (lane & 7)) * AP + kk + (((lane >> 3) & 1) << 3)]);
                mma_bf16(sacc[nt], a, bb[0], bb[1]);
            }
        }

        const bool diag = (jt == it);
        const int r0l = m0 + g, r1l = r0l + 8;
        #pragma unroll
        for (int nt = 0; nt < 8; nt++) {
            int c0 = nt * 8 + 2 * tg, c1 = c0 + 1;
            float s00 = sacc[nt][0] * 0.125f, s01 = sacc[nt][1] * 0.125f;
            float s10 = sacc[nt][2] * 0.125f, s11 = sacc[nt][3] * 0.125f;
            if (diag) {
                if (c0 > r0l) s00 = -1e30f;
                if (c1 > r0l) s01 = -1e30f;
                if (c0 > r1l) s10 = -1e30f;
                if (c1 > r1l) s11 = -1e30f;
            }
            Sf[r0l * SP + c0] = s00; Sf[r0l * SP + c1] = s01;
            Sf[r1l * SP + c0] = s10; Sf[r1l * SP + c1] = s11;
        }
        __syncwarp();

        {
            int row = m0 + (lane >> 1);
            int cbase = (lane & 1) * 32;
            float* srow = &Sf[row * SP + cbase];
            __nv_bfloat16* prow = &Pb[row * AP + cbase];
            float mloc = -1e30f;
            #pragma unroll
            for (int c = 0; c < 32; c++) mloc = fmaxf(mloc, srow[c]);
            mloc = fmaxf(mloc, __shfl_xor_sync(0xFFFFFFFFu, mloc, 1));
            float mOld = smM[row];
            float mNew = fmaxf(mOld, mloc);
            float sc = __expf(mOld - mNew);
            float s = 0.f;
            #pragma unroll
            for (int c = 0; c < 32; c++) {
                float e = __expf(srow[c] - mNew);
                prow[c] = __float2bfloat16(e);
                s += e;
            }
            s += __shfl_xor_sync(0xFFFFFFFFu, s, 1);
            if ((lane & 1) == 0) {
                smM[row]  = mNew;
                smL[row]  = smL[row] * sc + s;
                smSc[row] = sc;
            }
        }
        __syncwarp();

        {
            float sc0 = smSc[m0 + g], sc1 = smSc[m0 + g + 8];
            #pragma unroll
            for (int nt = 0; nt < 8; nt++) {
                acc[nt][0] *= sc0; acc[nt][1] *= sc0;
                acc[nt][2] *= sc1; acc[nt][3] *= sc1;
            }
        }
        #pragma unroll
        for (int kk = 0; kk < 64; kk += 16) {
            uint32_t a[4];
            ldsm_x4(a, &Pb[(m0 + (lane & 15)) * AP + kk + ((lane >> 4) << 3)]);
            #pragma unroll
            for (int nt = 0; nt < 8; nt++) {
                uint32_t bb[2];
                ldsm_x2t(bb, &Vs[(kk + (lane & 15)) * AP + nt * 8]);
                mma_bf16(acc[nt], a, bb[0], bb[1]);
            }
        }
        __syncthreads();
    }

    float inv0 = 1.f / smL[m0 + g];
    float inv1 = 1.f / smL[m0 + g + 8];
    __nv_bfloat16* O = d_hb + HB_ATTN;
    int tok0 = tokQ0 + m0 + g;
    #pragma unroll
    for (int nt = 0; nt < 8; nt++) {
        int c = h * 64 + nt * 8 + 2 * tg;
        *(__nv_bfloat162*)&O[(size_t)tok0 * D_ + c] =
            __floats2bfloat162_rn(acc[nt][0] * inv0, acc[nt][1] * inv0);
        *(__nv_bfloat162*)&O[(size_t)(tok0 + 8) * D_ + c] =
            __floats2bfloat162_rn(acc[nt][2] * inv1, acc[nt][3] * inv1);
    }
}

// ---------------------------------------------------------------------------
// 7. SwiGLU from fused U12 (vectorized bf16x2)
// ---------------------------------------------------------------------------
#define NPAIR (DFFP2_ / 2)

__global__ __launch_bounds__(256) void swiglu2_kernel()
{
    int i = blockIdx.x * 256 + threadIdx.x;
    if (i >= M_ * NPAIR) return;
    int m = i / NPAIR, p = i - m * NPAIR;
    __nv_bfloat162 r = __floats2bfloat162_rn(0.f, 0.f);
    if (p < DFF_ / 2) {
        const __nv_bfloat16* base = d_hb + HB_U12 + (size_t)m * LD12_;
        __nv_bfloat162 a2 = *(const __nv_bfloat162*)(base + 2 * p);
        __nv_bfloat162 c2 = *(const __nv_bfloat162*)(base + DFF_ + 2 * p);
        float a0 = __bfloat162float(a2.x), a1 = __bfloat162float(a2.y);
        float c0 = __bfloat162float(c2.x), c1 = __bfloat162float(c2.y);
        float v0 = a0 / (1.f + __expf(-a0)) * c0;
        float v1 = a1 / (1.f + __expf(-a1)) * c1;
        r = __floats2bfloat162_rn(v0, v1);
    }
    *(__nv_bfloat162*)(d_hb + HB_U + (size_t)m * DFFP2_ + 2 * p) = r;
}

// ---------------------------------------------------------------------------
// Launcher
// ---------------------------------------------------------------------------
extern "C" void kernel_launch(void* const* d_in, const int* in_sizes, int n_in,
                              void* d_out, int out_size)
{
    const float* x    = (const float*)d_in[0];
    const float* wr   = (const float*)d_in[1];
    const float* Wqkv = (const float*)d_in[2];
    const float* Wout = (const float*)d_in[3];
    const float* g1   = (const float*)d_in[4];
    const float* g2   = (const float*)d_in[5];
    const float* W1   = (const float*)d_in[6];
    const float* W2   = (const float*)d_in[7];
    const float* W3   = (const float*)d_in[8];
    float* out = (float*)d_out;

    float* ws = nullptr;
    __nv_bfloat16* hb = nullptr;
    cudaGetSymbolAddress((void**)&ws, d_ws);
    cudaGetSymbolAddress((void**)&hb, d_hb);
    cudaFuncSetAttribute(flash_attn_kernel,
                         cudaFuncAttributeMaxDynamicSharedMemorySize, FA_SMEM_BYTES);
    cudaFuncSetAttribute(bf16_gemm_nt,
                         cudaFuncAttributeMaxDynamicSharedMemorySize, G_SMEM_BYTES);

    auto gemm = [&](const __nv_bfloat16* A, const __nv_bfloat16* Bw, void* C,
                    const float* ADD, int M, int N, int K, int ldc, int mode) {
        dim3 grid((N + 127) / 128, M / 128);
        bf16_gemm_nt<<<grid, 256, G_SMEM_BYTES>>>(A, Bw, C, ADD, M, N, K, ldc, mode);
    };

    // router only (dot products)
    router_kernel<<<B_ * T_ / 4, 256>>>(x, wr);

    // top-k chunk sort + weight-prep half 1 + out=x copy half 1
    topk_sort_prep_kernel<<<32 + SORT_PREP_BLKS + SORT_COPY_BLKS, 256>>>(
        Wqkv, Wout, W1, W2, W3, x, out);
    // top-k merge + weight-prep half 2 + out=x copy half 2
    topk_merge_prep_kernel<<<B_ + MERGE_PREP_BLKS + MERGE_COPY_BLKS, 512>>>(
        Wqkv, Wout, W1, W2, W3, x, out);

    gather_rmsnorm_kernel<<<M_, 256>>>(x, g1);

    // QKV projection -> bf16
    gemm(hb + HB_H, hb + HB_WQKV, hb + HB_QKV, nullptr, M_, 3 * D_, D_, 3 * D_, 1);

    flash_attn_kernel<<<dim3(B_ * H_, 8), 128, FA_SMEM_BYTES>>>();

    // out projection + residual (XSEL) -> fp32 Y1
    gemm(hb + HB_ATTN, hb + HB_WOUT, ws + OFF_Y1, ws + OFF_XSEL, M_, D_, D_, D_, 0);

    rmsnorm2_kernel<<<M_, 256>>>(g2);

    // fused FFN up (W1|W2) -> bf16 U12
    gemm(hb + HB_H2, hb + HB_W12, hb + HB_U12, nullptr, M_, DFF2_, D_, LD12_, 1);
    swiglu2_kernel<<<(M_ * NPAIR + 255) / 256, 256>>>();

    // FFN down + residual, scattered directly into out (fused scatter)
    gemm(hb + HB_U, hb + HB_W3P, out, ws + OFF_Y1, M_, D_, DFFP2_, D_, 3);
}

// round 16
// speedup vs baseline: 1.0239x; 1.0239x over previous
#include <cuda_runtime.h>
#include <cuda_bf16.h>
#include <cstdint>
#include <cmath>

#define B_ 4
#define T_ 4096
#define D_ 1024
#define H_ 16
#define HD_ 64
#define CAP_ 512
#define M_ 2048
#define DFF_ 2730
#define DFF2_ 5460          // 2*DFF (fused W1|W2 GEMM N)
#define LD12_ 5472          // row pitch of fused U12 output (mult of 32)
#define DFFP2_ 2752         // padded K for W3 GEMM (mult of 32)

// ---------------------------------------------------------------------------
// fp32 workspace
// ---------------------------------------------------------------------------
constexpr size_t OFF_SCORES = 0;
constexpr size_t OFF_XSEL   = OFF_SCORES + (size_t)B_ * T_;
constexpr size_t OFF_Y1     = OFF_XSEL   + (size_t)M_ * D_;
constexpr size_t WS_TOTAL   = OFF_Y1     + (size_t)M_ * D_;

__device__ __align__(256) float d_ws[WS_TOTAL];

// bf16 workspace
constexpr size_t HB_H    = 0;
constexpr size_t HB_QKV  = HB_H    + (size_t)M_ * D_;
constexpr size_t HB_ATTN = HB_QKV  + (size_t)M_ * 3 * D_;
constexpr size_t HB_H2   = HB_ATTN + (size_t)M_ * D_;
constexpr size_t HB_U12  = HB_H2   + (size_t)M_ * D_;
constexpr size_t HB_U    = HB_U12  + (size_t)M_ * LD12_;
constexpr size_t HB_W3P  = HB_U    + (size_t)M_ * DFFP2_;
constexpr size_t HB_WQKV = HB_W3P  + (size_t)D_ * DFFP2_;
constexpr size_t HB_WOUT = HB_WQKV + (size_t)3 * D_ * D_;
constexpr size_t HB_W12  = HB_WOUT + (size_t)D_ * D_;
constexpr size_t HB_TOTAL= HB_W12  + (size_t)DFF2_ * D_;

__device__ __align__(256) __nv_bfloat16 d_hb[HB_TOTAL];
__device__ int d_idx[M_];
__device__ unsigned long long d_keys[B_ * T_];

// ---------------------------------------------------------------------------
// helpers
// ---------------------------------------------------------------------------
__device__ __forceinline__ void cp_async16(uint32_t dst, const void* src, bool valid) {
    int sz = valid ? 16 : 0;
    asm volatile("cp.async.cg.shared.global [%0], [%1], 16, %2;\n"
                 :: "r"(dst), "l"(src), "r"(sz));
}
__device__ __forceinline__ void ldsm_x4(uint32_t* r, const void* p) {
    uint32_t a = (uint32_t)__cvta_generic_to_shared(p);
    asm volatile("ldmatrix.sync.aligned.m8n8.x4.shared.b16 {%0,%1,%2,%3}, [%4];"
                 : "=r"(r[0]), "=r"(r[1]), "=r"(r[2]), "=r"(r[3]) : "r"(a));
}
__device__ __forceinline__ void ldsm_x2(uint32_t* r, const void* p) {
    uint32_t a = (uint32_t)__cvta_generic_to_shared(p);
    asm volatile("ldmatrix.sync.aligned.m8n8.x2.shared.b16 {%0,%1}, [%2];"
                 : "=r"(r[0]), "=r"(r[1]) : "r"(a));
}
__device__ __forceinline__ void ldsm_x2t(uint32_t* r, const void* p) {
    uint32_t a = (uint32_t)__cvta_generic_to_shared(p);
    asm volatile("ldmatrix.sync.aligned.m8n8.x2.trans.shared.b16 {%0,%1}, [%2];"
                 : "=r"(r[0]), "=r"(r[1]) : "r"(a));
}
__device__ __forceinline__ void mma_bf16(float* c, const uint32_t* a, uint32_t b0, uint32_t b1) {
    asm volatile(
        "mma.sync.aligned.m16n8k16.row.col.f32.bf16.bf16.f32 "
        "{%0,%1,%2,%3}, {%4,%5,%6,%7}, {%8,%9}, {%0,%1,%2,%3};\n"
        : "+f"(c[0]), "+f"(c[1]), "+f"(c[2]), "+f"(c[3])
        : "r"(a[0]), "r"(a[1]), "r"(a[2]), "r"(a[3]), "r"(b0), "r"(b1));
}

// ---------------------------------------------------------------------------
// block reduce (256 threads)
// ---------------------------------------------------------------------------
__device__ __forceinline__ float block_reduce_sum_256(float v, float* red)
{
    #pragma unroll
    for (int o = 16; o; o >>= 1) v += __shfl_xor_sync(0xFFFFFFFFu, v, o);
    if ((threadIdx.x & 31) == 0) red[threadIdx.x >> 5] = v;
    __syncthreads();
    float tot = 0.f;
    #pragma unroll
    for (int w = 0; w < 8; w++) tot += red[w];
    return tot;
}

// ---------------------------------------------------------------------------
// Weight prep work item (range-dispatched)
// ---------------------------------------------------------------------------
constexpr size_t WP_N1 = (size_t)3 * D_ * D_ / 4;            // Wqkv float4s
constexpr size_t WP_N2 = WP_N1 + (size_t)D_ * D_ / 4;        // + Wout
constexpr size_t WP_N3 = WP_N2 + (size_t)DFF2_ * D_ / 4;     // + W12
constexpr size_t WP_N4 = WP_N3 + (size_t)D_ * DFFP2_ / 2;    // + W3 (pair idx)
constexpr size_t WP_SPLIT = 1927680;                          // = 256*7530, ~half

__device__ __forceinline__ void weight_prep_item(size_t i,
                                                 const float* __restrict__ Wqkv,
                                                 const float* __restrict__ Wout,
                                                 const float* __restrict__ W1,
                                                 const float* __restrict__ W2,
                                                 const float* __restrict__ W3)
{
    if (i >= WP_N3) {
        size_t j = i - WP_N3;
        int n = (int)(j / (DFFP2_ / 2));
        int k2 = (int)(j - (size_t)n * (DFFP2_ / 2)) * 2;
        __nv_bfloat162 r;
        if (k2 < DFF_) {
            float2 v = *(const float2*)(W3 + (size_t)n * DFF_ + k2);
            r = __floats2bfloat162_rn(v.x, v.y);
        } else {
            r = __floats2bfloat162_rn(0.f, 0.f);
        }
        *(__nv_bfloat162*)(d_hb + HB_W3P + (size_t)n * DFFP2_ + k2) = r;
        return;
    }
    const float* src;
    __nv_bfloat162* dst;
    if (i < WP_N1) {
        src = (const float*)((const float4*)Wqkv + i);
        dst = (__nv_bfloat162*)(d_hb + HB_WQKV) + i * 2;
    } else if (i < WP_N2) {
        size_t j = i - WP_N1;
        src = (const float*)((const float4*)Wout + j);
        dst = (__nv_bfloat162*)(d_hb + HB_WOUT) + j * 2;
    } else {
        size_t j = i - WP_N2;
        int row = (int)(j >> 8);                // D_/4 = 256
        int c4  = (int)(j & 255);
        const float* s = (row < DFF_) ? (W1 + (size_t)row * D_)
                                      : (W2 + (size_t)(row - DFF_) * D_);
        src = s + c4 * 4;
        dst = (__nv_bfloat162*)(d_hb + HB_W12 + (size_t)row * D_ + c4 * 4);
    }
    float4 v = *(const float4*)src;
    dst[0] = __floats2bfloat162_rn(v.x, v.y);
    dst[1] = __floats2bfloat162_rn(v.z, v.w);
}

// ---------------------------------------------------------------------------
// 1. Fused copy (out = x) + router scores. 4 tokens per block.
// ---------------------------------------------------------------------------
__global__ __launch_bounds__(256) void copy_router_kernel(float* __restrict__ out,
                                                          const float* __restrict__ x,
                                                          const float* __restrict__ wr)
{
    __shared__ float red[4][8];
    int tok0 = blockIdx.x * 4;
    int tid = threadIdx.x;
    float4 w = ((const float4*)wr)[tid];

    float4 v[4];
    #pragma unroll
    for (int t = 0; t < 4; t++)
        v[t] = ((const float4*)(x + (size_t)(tok0 + t) * D_))[tid];
    #pragma unroll
    for (int t = 0; t < 4; t++)
        ((float4*)(out + (size_t)(tok0 + t) * D_))[tid] = v[t];

    #pragma unroll
    for (int t = 0; t < 4; t++) {
        float dot = v[t].x * w.x + v[t].y * w.y + v[t].z * w.z + v[t].w * w.w;
        #pragma unroll
        for (int o = 16; o; o >>= 1) dot += __shfl_xor_sync(0xFFFFFFFFu, dot, o);
        if ((tid & 31) == 0) red[t][tid >> 5] = dot;
    }
    __syncthreads();
    if (tid < 4) {
        float s = 0.f;
        #pragma unroll
        for (int wv = 0; wv < 8; wv++) s += red[tid][wv];
        d_ws[OFF_SCORES + tok0 + tid] = s;
    }
}

// ---------------------------------------------------------------------------
// 2a. Top-k chunk sort (blocks 0-31) + weight-prep half 1 (blocks 32+)
// ---------------------------------------------------------------------------
__global__ __launch_bounds__(256) void topk_sort_prep_kernel(const float* __restrict__ Wqkv,
                                                             const float* __restrict__ Wout,
                                                             const float* __restrict__ W1,
                                                             const float* __restrict__ W2,
                                                             const float* __restrict__ W3)
{
    __shared__ unsigned long long key[512];

    if (blockIdx.x >= 32) {
        size_t i = (size_t)(blockIdx.x - 32) * 256 + threadIdx.x;
        if (i < WP_SPLIT)
            weight_prep_item(i, Wqkv, Wout, W1, W2, W3);
        return;
    }

    int chunk = blockIdx.x;
    int b = chunk >> 3;
    int c0 = (chunk & 7) * 512;

    for (int t = threadIdx.x; t < 512; t += 256) {
        int gi = c0 + t;
        float s = d_ws[OFF_SCORES + (size_t)b * T_ + gi];
        unsigned int u = __float_as_uint(s);
        u = (u & 0x80000000u) ? ~u : (u | 0x80000000u);
        key[t] = ((unsigned long long)u << 32) | (unsigned int)(0xFFFFFFFFu - (unsigned)gi);
    }
    __syncthreads();
    for (int k = 2; k <= 512; k <<= 1) {
        for (int j = k >> 1; j > 0; j >>= 1) {
            for (int t = threadIdx.x; t < 512; t += 256) {
                int l = t ^ j;
                if (l > t) {
                    unsigned long long a = key[t], c = key[l];
                    bool desc = ((t & k) == 0);
                    if (desc ? (a < c) : (a > c)) { key[t] = c; key[l] = a; }
                }
            }
            __syncthreads();
        }
    }
    for (int t = threadIdx.x; t < 512; t += 256)
        d_keys[(size_t)b * T_ + c0 + t] = key[t];
}

// ---------------------------------------------------------------------------
// 2b. Top-k merge (blocks 0-3) + weight-prep half 2 (blocks 4+)
// ---------------------------------------------------------------------------
__global__ __launch_bounds__(512) void topk_merge_prep_kernel(const float* __restrict__ Wqkv,
                                                              const float* __restrict__ Wout,
                                                              const float* __restrict__ W1,
                                                              const float* __restrict__ W2,
                                                              const float* __restrict__ W3)
{
    __shared__ unsigned long long key[T_];

    if (blockIdx.x >= B_) {
        size_t i = WP_SPLIT + (size_t)(blockIdx.x - B_) * 512 + threadIdx.x;
        if (i < WP_N4)
            weight_prep_item(i, Wqkv, Wout, W1, W2, W3);
        return;
    }

    int b = blockIdx.x;
    for (int t = threadIdx.x; t < T_; t += 512)
        key[t] = d_keys[(size_t)b * T_ + t];
    __syncthreads();

    #pragma unroll
    for (int r = 0; r < 3; r++) {
        int pairs = 4 >> r;
        int stride = 1024 << r;
        int half = 512 << r;
        for (int e = threadIdx.x; e < pairs * 512; e += 512) {
            int p = e >> 9, i = e & 511;
            int base = p * stride;
            unsigned long long a = key[base + i];
            unsigned long long bb = key[base + half + 511 - i];
            if (bb > a) key[base + i] = bb;
        }
        __syncthreads();
        for (int j = 256; j > 0; j >>= 1) {
            for (int e = threadIdx.x; e < pairs * 256; e += 512) {
                int p = e >> 8, q = e & 255;
                int i = ((q & ~(j - 1)) << 1) | (q & (j - 1));
                int base = p * stride;
                unsigned long long a = key[base + i], c = key[base + i + j];
                if (a < c) { key[base + i] = c; key[base + i + j] = a; }
            }
            __syncthreads();
        }
    }
    for (int t = threadIdx.x; t < CAP_; t += 512)
        d_idx[b * CAP_ + t] = (int)(0xFFFFFFFFu - (unsigned int)(key[t] & 0xFFFFFFFFu));
}

// ---------------------------------------------------------------------------
// 3. Gather + RMSNorm (writes XSEL fp32 + H bf16)
// ---------------------------------------------------------------------------
__global__ __launch_bounds__(256) void gather_rmsnorm_kernel(const float* __restrict__ x,
                                                             const float* __restrict__ g)
{
    __shared__ float red[8];
    int row = blockIdx.x;
    int b = row >> 9;
    int t = d_idx[row];
    int tid = threadIdx.x;
    float4 v = ((const float4*)(x + ((size_t)b * T_ + t) * D_))[tid];
    float ss = v.x*v.x + v.y*v.y + v.z*v.z + v.w*v.w;
    float tot = block_reduce_sum_256(ss, red);
    float rinv = rsqrtf(tot * (1.f / D_) + 1e-6f);
    float4 gv = ((const float4*)g)[tid];
    ((float4*)(d_ws + OFF_XSEL + (size_t)row * D_))[tid] = v;
    __nv_bfloat162* hb = (__nv_bfloat162*)(d_hb + HB_H + (size_t)row * D_);
    hb[tid * 2]     = __floats2bfloat162_rn(v.x * rinv * gv.x, v.y * rinv * gv.y);
    hb[tid * 2 + 1] = __floats2bfloat162_rn(v.z * rinv * gv.z, v.w * rinv * gv.w);
}

// ---------------------------------------------------------------------------
// 4. RMSNorm y1 -> H2b
// ---------------------------------------------------------------------------
__global__ __launch_bounds__(256) void rmsnorm2_kernel(const float* __restrict__ g)
{
    __shared__ float red[8];
    int row = blockIdx.x;
    int tid = threadIdx.x;
    float4 v = ((const float4*)(d_ws + OFF_Y1 + (size_t)row * D_))[tid];
    float ss = v.x*v.x + v.y*v.y + v.z*v.z + v.w*v.w;
    float tot = block_reduce_sum_256(ss, red);
    float rinv = rsqrtf(tot * (1.f / D_) + 1e-6f);
    float4 gv = ((const float4*)g)[tid];
    __nv_bfloat162* hb = (__nv_bfloat162*)(d_hb + HB_H2 + (size_t)row * D_);
    hb[tid * 2]     = __floats2bfloat162_rn(v.x * rinv * gv.x, v.y * rinv * gv.y);
    hb[tid * 2 + 1] = __floats2bfloat162_rn(v.z * rinv * gv.z, v.w * rinv * gv.w);
}

// ---------------------------------------------------------------------------
// 5. BF16 mma.sync GEMM (NT) — round-9 exact mainloop (big GEMMs).
//    mode 0: fp32 out (+ADD). mode 1: bf16 out. mode 3: scatter via d_idx.
// ---------------------------------------------------------------------------
#define GBK2 32
#define BPITCH 40
#define G_NST 3
constexpr int G_STAGE_HALVES = 2 * 128 * BPITCH;
constexpr int G_SMEM_BYTES   = G_NST * G_STAGE_HALVES * 2;   // 61440

__global__ __launch_bounds__(256, 2) void bf16_gemm_nt(const __nv_bfloat16* __restrict__ A,
                                                       const __nv_bfloat16* __restrict__ Bw,
                                                       void* __restrict__ Cv,
                                                       const float* __restrict__ ADD,
                                                       int M, int N, int K, int ldc,
                                                       int mode)
{
    extern __shared__ __nv_bfloat16 gs[];

    const int tid  = threadIdx.x;
    const int lane = tid & 31, warp = tid >> 5;
    const int g    = lane >> 2, tg = lane & 3;
    const int wm   = warp >> 2;
    const int wn   = warp & 3;
    const int row0 = blockIdx.y * 128;
    const int col0 = blockIdx.x * 128;
    const int nk   = K / GBK2;

    float acc[4][4][4];
    #pragma unroll
    for (int i = 0; i < 4; i++)
        #pragma unroll
        for (int j = 0; j < 4; j++)
            #pragma unroll
            for (int r = 0; r < 4; r++) acc[i][j][r] = 0.f;

    auto issue = [&](int s, int ki) {
        __nv_bfloat16* As = gs + s * G_STAGE_HALVES;
        __nv_bfloat16* Bs = As + 128 * BPITCH;
        int k0 = ki * GBK2;
        #pragma unroll
        for (int i = 0; i < 2; i++) {
            int c = tid + 256 * i;
            int r = c >> 2, off = (c & 3) * 8;
            cp_async16((uint32_t)__cvta_generic_to_shared(&As[r * BPITCH + off]),
                       A + (size_t)(row0 + r) * K + k0 + off, true);
            cp_async16((uint32_t)__cvta_generic_to_shared(&Bs[r * BPITCH + off]),
                       Bw + (size_t)(col0 + r) * K + k0 + off, (col0 + r) < N);
        }
        asm volatile("cp.async.commit_group;\n");
    };

    issue(0, 0);
    issue(1, 1);
    issue(2, 2);

    for (int i = 0; i < nk; i++) {
        int s = i - (i / G_NST) * G_NST;
        int issued = (i + G_NST < nk) ? (i + G_NST) : nk;
        int pend = issued - i - 1;
        if (pend >= 2)      asm volatile("cp.async.wait_group 2;\n");
        else if (pend == 1) asm volatile("cp.async.wait_group 1;\n");
        else                asm volatile("cp.async.wait_group 0;\n");
        __syncthreads();

        const __nv_bfloat16* As = gs + s * G_STAGE_HALVES;
        const __nv_bfloat16* Bs = As + 128 * BPITCH;

        #pragma unroll
        for (int kk = 0; kk < GBK2; kk += 16) {
            uint32_t af[4][4];
            #pragma unroll
            for (int mt = 0; mt < 4; mt++)
                ldsm_x4(af[mt], &As[(wm * 64 + mt * 16 + (lane & 15)) * BPITCH
                                    + kk + ((lane >> 4) << 3)]);
            #pragma unroll
            for (int pb = 0; pb < 2; pb++) {
                uint32_t bq[4];
                ldsm_x4(bq, &Bs[(wn * 32 + pb * 16 + (lane & 7) + ((lane >> 3) & 1) * 8) * BPITCH
                                + kk + ((lane >> 4) << 3)]);
                #pragma unroll
                for (int mt = 0; mt < 4; mt++) {
                    mma_bf16(acc[mt][pb * 2],     af[mt], bq[0], bq[2]);
                    mma_bf16(acc[mt][pb * 2 + 1], af[mt], bq[1], bq[3]);
                }
            }
        }
        __syncthreads();

        if (i + G_NST < nk) issue(s, i + G_NST);
    }

    #pragma unroll
    for (int mt = 0; mt < 4; mt++) {
        int r1 = row0 + wm * 64 + mt * 16 + g;
        int r2 = r1 + 8;
        size_t or1 = (size_t)r1, or2 = (size_t)r2;
        if (mode == 3) {
            or1 = (size_t)((r1 >> 9) * T_ + d_idx[r1]);
            or2 = (size_t)((r2 >> 9) * T_ + d_idx[r2]);
        }
        #pragma unroll
        for (int nt = 0; nt < 4; nt++) {
            int c = col0 + wn * 32 + nt * 8 + 2 * tg;
            if (c < N) {
                float2 v0 = make_float2(acc[mt][nt][0], acc[mt][nt][1]);
                float2 v1 = make_float2(acc[mt][nt][2], acc[mt][nt][3]);
                if (ADD) {
                    float2 a0 = *(const float2*)&ADD[(size_t)r1 * ldc + c];
                    float2 a1 = *(const float2*)&ADD[(size_t)r2 * ldc + c];
                    v0.x += a0.x; v0.y += a0.y;
                    v1.x += a1.x; v1.y += a1.y;
                }
                if (mode == 1) {
                    __nv_bfloat16* C = (__nv_bfloat16*)Cv;
                    *(__nv_bfloat162*)&C[(size_t)r1 * ldc + c] = __floats2bfloat162_rn(v0.x, v0.y);
                    *(__nv_bfloat162*)&C[(size_t)r2 * ldc + c] = __floats2bfloat162_rn(v1.x, v1.y);
                } else {
                    float* C = (float*)Cv;
                    *(float2*)&C[or1 * ldc + c] = v0;
                    *(float2*)&C[or2 * ldc + c] = v1;
                }
            }
        }
    }
}

// ---------------------------------------------------------------------------
// 5b. BM=64 GEMM variant for narrow-N GEMMs (Wout, W3-down).
//     256 threads, 1x8 warp grid, warp tile 64x16. Same kk/mma order per
//     output element -> bit-identical results. N must be mult of 128.
// ---------------------------------------------------------------------------
constexpr int G64_STAGE_HALVES = (64 + 128) * BPITCH;        // 7680
constexpr int G64_SMEM_BYTES   = G_NST * G64_STAGE_HALVES * 2;  // 46080

__global__ __launch_bounds__(256, 2) void bf16_gemm_nt_m64(const __nv_bfloat16* __restrict__ A,
                                                           const __nv_bfloat16* __restrict__ Bw,
                                                           void* __restrict__ Cv,
                                                           const float* __restrict__ ADD,
                                                           int M, int N, int K, int ldc,
                                                           int mode)
{
    extern __shared__ __nv_bfloat16 gs[];

    const int tid  = threadIdx.x;
    const int lane = tid & 31, warp = tid >> 5;   // warp 0..7
    const int g    = lane >> 2, tg = lane & 3;
    const int wn   = warp;                        // 8 warps across N
    const int row0 = blockIdx.y * 64;
    const int col0 = blockIdx.x * 128;
    const int nk   = K / GBK2;

    float acc[4][2][4];
    #pragma unroll
    for (int i = 0; i < 4; i++)
        #pragma unroll
        for (int j = 0; j < 2; j++)
            #pragma unroll
            for (int r = 0; r < 4; r++) acc[i][j][r] = 0.f;

    auto issue = [&](int s, int ki) {
        __nv_bfloat16* As = gs + s * G64_STAGE_HALVES;
        __nv_bfloat16* Bs = As + 64 * BPITCH;
        int k0 = ki * GBK2;
        #pragma unroll
        for (int i = 0; i < 3; i++) {
            int c = tid + 256 * i;                 // 0..767
            if (c < 256) {
                int r = c >> 2, off = (c & 3) * 8;
                cp_async16((uint32_t)__cvta_generic_to_shared(&As[r * BPITCH + off]),
                           A + (size_t)(row0 + r) * K + k0 + off, true);
            } else {
                int j = c - 256;
                int r = j >> 2, off = (j & 3) * 8;
                cp_async16((uint32_t)__cvta_generic_to_shared(&Bs[r * BPITCH + off]),
                           Bw + (size_t)(col0 + r) * K + k0 + off, (col0 + r) < N);
            }
        }
        asm volatile("cp.async.commit_group;\n");
    };

    issue(0, 0);
    issue(1, 1);
    issue(2, 2);

    for (int i = 0; i < nk; i++) {
        int s = i - (i / G_NST) * G_NST;
        int issued = (i + G_NST < nk) ? (i + G_NST) : nk;
        int pend = issued - i - 1;
        if (pend >= 2)      asm volatile("cp.async.wait_group 2;\n");
        else if (pend == 1) asm volatile("cp.async.wait_group 1;\n");
        else                asm volatile("cp.async.wait_group 0;\n");
        __syncthreads();

        const __nv_bfloat16* As = gs + s * G64_STAGE_HALVES;
        const __nv_bfloat16* Bs = As + 64 * BPITCH;

        #pragma unroll
        for (int kk = 0; kk < GBK2; kk += 16) {
            uint32_t af[4][4];
            #pragma unroll
            for (int mt = 0; mt < 4; mt++)
                ldsm_x4(af[mt], &As[(mt * 16 + (lane & 15)) * BPITCH
                                    + kk + ((lane >> 4) << 3)]);
            uint32_t bq[4];
            ldsm_x4(bq, &Bs[(wn * 16 + (lane & 7) + ((lane >> 3) & 1) * 8) * BPITCH
                            + kk + ((lane >> 4) << 3)]);
            #pragma unroll
            for (int mt = 0; mt < 4; mt++) {
                mma_bf16(acc[mt][0], af[mt], bq[0], bq[2]);
                mma_bf16(acc[mt][1], af[mt], bq[1], bq[3]);
            }
        }
        __syncthreads();

        if (i + G_NST < nk) issue(s, i + G_NST);
    }

    #pragma unroll
    for (int mt = 0; mt < 4; mt++) {
        int r1 = row0 + mt * 16 + g;
        int r2 = r1 + 8;
        size_t or1 = (size_t)r1, or2 = (size_t)r2;
        if (mode == 3) {
            or1 = (size_t)((r1 >> 9) * T_ + d_idx[r1]);
            or2 = (size_t)((r2 >> 9) * T_ + d_idx[r2]);
        }
        #pragma unroll
        for (int nt = 0; nt < 2; nt++) {
            int c = col0 + wn * 16 + nt * 8 + 2 * tg;
            if (c < N) {
                float2 v0 = make_float2(acc[mt][nt][0], acc[mt][nt][1]);
                float2 v1 = make_float2(acc[mt][nt][2], acc[mt][nt][3]);
                if (ADD) {
                    float2 a0 = *(const float2*)&ADD[(size_t)r1 * ldc + c];
                    float2 a1 = *(const float2*)&ADD[(size_t)r2 * ldc + c];
                    v0.x += a0.x; v0.y += a0.y;
                    v1.x += a1.x; v1.y += a1.y;
                }
                if (mode == 1) {
                    __nv_bfloat16* C = (__nv_bfloat16*)Cv;
                    *(__nv_bfloat162*)&C[(size_t)r1 * ldc + c] = __floats2bfloat162_rn(v0.x, v0.y);
                    *(__nv_bfloat162*)&C[(size_t)r2 * ldc + c] = __floats2bfloat162_rn(v1.x, v1.y);
                } else {
                    float* C = (float*)Cv;
                    *(float2*)&C[or1 * ldc + c] = v0;
                    *(float2*)&C[or2 * ldc + c] = v1;
                }
            }
        }
    }
}

// ---------------------------------------------------------------------------
// 6. Fused flash attention (bf16 mma.sync, validated round 4)
// ---------------------------------------------------------------------------
#define AP 72
#define SP 68
constexpr int FA_SMEM_BYTES = (4 * 64 * AP) * 2 + (64 * SP + 3 * 64) * 4;

__global__ __launch_bounds__(128) void flash_attn_kernel()
{
    extern __shared__ char fsm_raw[];
    __nv_bfloat16* Qs = (__nv_bfloat16*)fsm_raw;
    __nv_bfloat16* Ks = Qs + 64 * AP;
    __nv_bfloat16* Vs = Ks + 64 * AP;
    __nv_bfloat16* Pb = Vs + 64 * AP;
    float* Sf   = (float*)(Pb + 64 * AP);
    float* smM  = Sf + 64 * SP;
    float* smL  = smM + 64;
    float* smSc = smL + 64;

    const int bh = blockIdx.x;
    const int it = 7 - blockIdx.y;
    const int b  = bh >> 4, h = bh & 15;
    const int tid = threadIdx.x;
    const int lane = tid & 31, w = tid >> 5;
    const int g = lane >> 2, tg = lane & 3;
    const int m0 = w * 16;

    const __nv_bfloat16* qkv = d_hb + HB_QKV;
    const int tokQ0 = b * CAP_ + it * 64;

    #pragma unroll
    for (int i = 0; i < 4; i++) {
        int c = tid + 128 * i;
        int r = c >> 3, off = (c & 7) * 8;
        cp_async16((uint32_t)__cvta_generic_to_shared(&Qs[r * AP + off]),
                   qkv + (size_t)(tokQ0 + r) * (3 * D_) + h * 64 + off, true);
    }
    asm volatile("cp.async.commit_group;\n");

    if (tid < 64) { smM[tid] = -1e30f; smL[tid] = 0.f; }

    float acc[8][4];
    #pragma unroll
    for (int nt = 0; nt < 8; nt++)
        #pragma unroll
        for (int r = 0; r < 4; r++) acc[nt][r] = 0.f;

    for (int jt = 0; jt <= it; jt++) {
        const int tokK0 = b * CAP_ + jt * 64;
        #pragma unroll
        for (int i = 0; i < 4; i++) {
            int c = tid + 128 * i;
            int r = c >> 3, off = (c & 7) * 8;
            cp_async16((uint32_t)__cvta_generic_to_shared(&Ks[r * AP + off]),
                       qkv + (size_t)(tokK0 + r) * (3 * D_) + D_ + h * 64 + off, true);
            cp_async16((uint32_t)__cvta_generic_to_shared(&Vs[r * AP + off]),
                       qkv + (size_t)(tokK0 + r) * (3 * D_) + 2 * D_ + h * 64 + off, true);
        }
        asm volatile("cp.async.commit_group;\n");
        asm volatile("cp.async.wait_group 0;\n");
        __syncthreads();

        float sacc[8][4];
        #pragma unroll
        for (int nt = 0; nt < 8; nt++)
            #pragma unroll
            for (int r = 0; r < 4; r++) sacc[nt][r] = 0.f;

        #pragma unroll
        for (int kk = 0; kk < 64; kk += 16) {
            uint32_t a[4];
            ldsm_x4(a, &Qs[(m0 + (lane & 15)) * AP + kk + ((lane >> 4) << 3)]);
            #pragma unroll
            for (int nt = 0; nt < 8; nt++) {
                uint32_t bb[2];
                ldsm_x2(bb, &Ks[(nt * 8 + (lane & 7)) * AP + kk + (((lane >> 3) & 1) << 3)]);
                mma_bf16(sacc[nt], a, bb[0], bb[1]);
            }
        }

        const bool diag = (jt == it);
        const int r0l = m0 + g, r1l = r0l + 8;
        #pragma unroll
        for (int nt = 0; nt < 8; nt++) {
            int c0 = nt * 8 + 2 * tg, c1 = c0 + 1;
            float s00 = sacc[nt][0] * 0.125f, s01 = sacc[nt][1] * 0.125f;
            float s10 = sacc[nt][2] * 0.125f, s11 = sacc[nt][3] * 0.125f;
            if (diag) {
                if (c0 > r0l) s00 = -1e30f;
                if (c1 > r0l) s01 = -1e30f;
                if (c0 > r1l) s10 = -1e30f;
                if (c1 > r1l) s11 = -1e30f;
            }
            Sf[r0l * SP + c0] = s00; Sf[r0l * SP + c1] = s01;
            Sf[r1l * SP + c0] = s10; Sf[r1l * SP + c1] = s11;
        }
        __syncwarp();

        {
            int row = m0 + (lane >> 1);
            int cbase = (lane & 1) * 32;
            float* srow = &Sf[row * SP + cbase];
            __nv_bfloat16* prow = &Pb[row * AP + cbase];
            float mloc = -1e30f;
            #pragma unroll
            for (int c = 0; c < 32; c++) mloc = fmaxf(mloc, srow[c]);
            mloc = fmaxf(mloc, __shfl_xor_sync(0xFFFFFFFFu, mloc, 1));
            float mOld = smM[row];
            float mNew = fmaxf(mOld, mloc);
            float sc = __expf(mOld - mNew);
            float s = 0.f;
            #pragma unroll
            for (int c = 0; c < 32; c++) {
                float e = __expf(srow[c] - mNew);
                prow[c] = __float2bfloat16(e);
                s += e;
            }
            s += __shfl_xor_sync(0xFFFFFFFFu, s, 1);
            if ((lane & 1) == 0) {
                smM[row]  = mNew;
                smL[row]  = smL[row] * sc + s;
                smSc[row] = sc;
            }
        }
        __syncwarp();

        {
            float sc0 = smSc[m0 + g], sc1 = smSc[m0 + g + 8];
            #pragma unroll
            for (int nt = 0; nt < 8; nt++) {
                acc[nt][0] *= sc0; acc[nt][1] *= sc0;
                acc[nt][2] *= sc1; acc[nt][3] *= sc1;
            }
        }
        #pragma unroll
        for (int kk = 0; kk < 64; kk += 16) {
            uint32_t a[4];
            ldsm_x4(a, &Pb[(m0 + (lane & 15)) * AP + kk + ((lane >> 4) << 3)]);
            #pragma unroll
            for (int nt = 0; nt < 8; nt++) {
                uint32_t bb[2];
                ldsm_x2t(bb, &Vs[(kk + (lane & 15)) * AP + nt * 8]);
                mma_bf16(acc[nt], a, bb[0], bb[1]);
            }
        }
        __syncthreads();
    }

    float inv0 = 1.f / smL[m0 + g];
    float inv1 = 1.f / smL[m0 + g + 8];
    __nv_bfloat16* O = d_hb + HB_ATTN;
    int tok0 = tokQ0 + m0 + g;
    #pragma unroll
    for (int nt = 0; nt < 8; nt++) {
        int c = h * 64 + nt * 8 + 2 * tg;
        *(__nv_bfloat162*)&O[(size_t)tok0 * D_ + c] =
            __floats2bfloat162_rn(acc[nt][0] * inv0, acc[nt][1] * inv0);
        *(__nv_bfloat162*)&O[(size_t)(tok0 + 8) * D_ + c] =
            __floats2bfloat162_rn(acc[nt][2] * inv1, acc[nt][3] * inv1);
    }
}

// ---------------------------------------------------------------------------
// 7. SwiGLU from fused U12 (vectorized bf16x2)
// ---------------------------------------------------------------------------
#define NPAIR (DFFP2_ / 2)

__global__ __launch_bounds__(256) void swiglu2_kernel()
{
    int i = blockIdx.x * 256 + threadIdx.x;
    if (i >= M_ * NPAIR) return;
    int m = i / NPAIR, p = i - m * NPAIR;
    __nv_bfloat162 r = __floats2bfloat162_rn(0.f, 0.f);
    if (p < DFF_ / 2) {
        const __nv_bfloat16* base = d_hb + HB_U12 + (size_t)m * LD12_;
        __nv_bfloat162 a2 = *(const __nv_bfloat162*)(base + 2 * p);
        __nv_bfloat162 c2 = *(const __nv_bfloat162*)(base + DFF_ + 2 * p);
        float a0 = __bfloat162float(a2.x), a1 = __bfloat162float(a2.y);
        float c0 = __bfloat162float(c2.x), c1 = __bfloat162float(c2.y);
        float v0 = a0 / (1.f + __expf(-a0)) * c0;
        float v1 = a1 / (1.f + __expf(-a1)) * c1;
        r = __floats2bfloat162_rn(v0, v1);
    }
    *(__nv_bfloat162*)(d_hb + HB_U + (size_t)m * DFFP2_ + 2 * p) = r;
}

// ---------------------------------------------------------------------------
// Launcher
// ---------------------------------------------------------------------------
extern "C" void kernel_launch(void* const* d_in, const int* in_sizes, int n_in,
                              void* d_out, int out_size)
{
    const float* x    = (const float*)d_in[0];
    const float* wr   = (const float*)d_in[1];
    const float* Wqkv = (const float*)d_in[2];
    const float* Wout = (const float*)d_in[3];
    const float* g1   = (const float*)d_in[4];
    const float* g2   = (const float*)d_in[5];
    const float* W1   = (const float*)d_in[6];
    const float* W2   = (const float*)d_in[7];
    const float* W3   = (const float*)d_in[8];
    float* out = (float*)d_out;

    float* ws = nullptr;
    __nv_bfloat16* hb = nullptr;
    cudaGetSymbolAddress((void**)&ws, d_ws);
    cudaGetSymbolAddress((void**)&hb, d_hb);
    cudaFuncSetAttribute(flash_attn_kernel,
                         cudaFuncAttributeMaxDynamicSharedMemorySize, FA_SMEM_BYTES);
    cudaFuncSetAttribute(bf16_gemm_nt,
                         cudaFuncAttributeMaxDynamicSharedMemorySize, G_SMEM_BYTES);
    cudaFuncSetAttribute(bf16_gemm_nt_m64,
                         cudaFuncAttributeMaxDynamicSharedMemorySize, G64_SMEM_BYTES);

    auto gemm = [&](const __nv_bfloat16* A, const __nv_bfloat16* Bw, void* C,
                    const float* ADD, int M, int N, int K, int ldc, int mode) {
        dim3 grid((N + 127) / 128, M / 128);
        bf16_gemm_nt<<<grid, 256, G_SMEM_BYTES>>>(A, Bw, C, ADD, M, N, K, ldc, mode);
    };
    auto gemm64 = [&](const __nv_bfloat16* A, const __nv_bfloat16* Bw, void* C,
                      const float* ADD, int M, int N, int K, int ldc, int mode) {
        dim3 grid((N + 127) / 128, M / 64);
        bf16_gemm_nt_m64<<<grid, 256, G64_SMEM_BYTES>>>(A, Bw, C, ADD, M, N, K, ldc, mode);
    };

    // fused copy+router (reads x once); overlapped top-k + weight-prep
    copy_router_kernel<<<B_ * T_ / 4, 256>>>(out, x, wr);
    topk_sort_prep_kernel<<<32 + (int)(WP_SPLIT / 256), 256>>>(Wqkv, Wout, W1, W2, W3);
    topk_merge_prep_kernel<<<B_ + (int)((WP_N4 - WP_SPLIT) / 512), 512>>>(Wqkv, Wout, W1, W2, W3);

    gather_rmsnorm_kernel<<<M_, 256>>>(x, g1);

    // QKV projection -> bf16 (big kernel)
    gemm(hb + HB_H, hb + HB_WQKV, hb + HB_QKV, nullptr, M_, 3 * D_, D_, 3 * D_, 1);

    flash_attn_kernel<<<dim3(B_ * H_, 8), 128, FA_SMEM_BYTES>>>();

    // out projection + residual (XSEL) -> fp32 Y1 (BM=64 variant, 256 CTAs)
    gemm64(hb + HB_ATTN, hb + HB_WOUT, ws + OFF_Y1, ws + OFF_XSEL, M_, D_, D_, D_, 0);

    rmsnorm2_kernel<<<M_, 256>>>(g2);

    // fused FFN up (W1|W2) -> bf16 U12 (big kernel)
    gemm(hb + HB_H2, hb + HB_W12, hb + HB_U12, nullptr, M_, DFF2_, D_, LD12_, 1);
    swiglu2_kernel<<<(M_ * NPAIR + 255) / 256, 256>>>();

    // FFN down + residual, scattered into out (BM=64 variant, 256 CTAs)
    gemm64(hb + HB_U, hb + HB_W3P, out, ws + OFF_Y1, M_, D_, DFFP2_, D_, 3);
}

// round 17
// speedup vs baseline: 1.0347x; 1.0106x over previous
#include <cuda_runtime.h>
#include <cuda_bf16.h>
#include <cstdint>
#include <cmath>

#define B_ 4
#define T_ 4096
#define D_ 1024
#define H_ 16
#define HD_ 64
#define CAP_ 512
#define M_ 2048
#define DFF_ 2730
#define DFF2_ 5460          // 2*DFF
#define DFF2P_ 5504         // interleaved W12 rows padded to 43*128
#define DFFP2_ 2752         // U width / W3 GEMM K (= DFF2P_/2)

// ---------------------------------------------------------------------------
// fp32 workspace
// ---------------------------------------------------------------------------
constexpr size_t OFF_SCORES = 0;
constexpr size_t OFF_XSEL   = OFF_SCORES + (size_t)B_ * T_;
constexpr size_t OFF_Y1     = OFF_XSEL   + (size_t)M_ * D_;
constexpr size_t WS_TOTAL   = OFF_Y1     + (size_t)M_ * D_;

__device__ __align__(256) float d_ws[WS_TOTAL];

// bf16 workspace
constexpr size_t HB_H    = 0;
constexpr size_t HB_QKV  = HB_H    + (size_t)M_ * D_;
constexpr size_t HB_ATTN = HB_QKV  + (size_t)M_ * 3 * D_;
constexpr size_t HB_H2   = HB_ATTN + (size_t)M_ * D_;
constexpr size_t HB_U    = HB_H2   + (size_t)M_ * D_;
constexpr size_t HB_W3P  = HB_U    + (size_t)M_ * DFFP2_;
constexpr size_t HB_WQKV = HB_W3P  + (size_t)D_ * DFFP2_;
constexpr size_t HB_WOUT = HB_WQKV + (size_t)3 * D_ * D_;
constexpr size_t HB_W12  = HB_WOUT + (size_t)D_ * D_;
constexpr size_t HB_TOTAL= HB_W12  + (size_t)DFF2P_ * D_;

__device__ __align__(256) __nv_bfloat16 d_hb[HB_TOTAL];
__device__ int d_idx[M_];
__device__ unsigned long long d_keys[B_ * T_];

// ---------------------------------------------------------------------------
// helpers
// ---------------------------------------------------------------------------
__device__ __forceinline__ void cp_async16(uint32_t dst, const void* src, bool valid) {
    int sz = valid ? 16 : 0;
    asm volatile("cp.async.cg.shared.global [%0], [%1], 16, %2;\n"
                 :: "r"(dst), "l"(src), "r"(sz));
}
__device__ __forceinline__ void ldsm_x4(uint32_t* r, const void* p) {
    uint32_t a = (uint32_t)__cvta_generic_to_shared(p);
    asm volatile("ldmatrix.sync.aligned.m8n8.x4.shared.b16 {%0,%1,%2,%3}, [%4];"
                 : "=r"(r[0]), "=r"(r[1]), "=r"(r[2]), "=r"(r[3]) : "r"(a));
}
__device__ __forceinline__ void ldsm_x2(uint32_t* r, const void* p) {
    uint32_t a = (uint32_t)__cvta_generic_to_shared(p);
    asm volatile("ldmatrix.sync.aligned.m8n8.x2.shared.b16 {%0,%1}, [%2];"
                 : "=r"(r[0]), "=r"(r[1]) : "r"(a));
}
__device__ __forceinline__ void ldsm_x2t(uint32_t* r, const void* p) {
    uint32_t a = (uint32_t)__cvta_generic_to_shared(p);
    asm volatile("ldmatrix.sync.aligned.m8n8.x2.trans.shared.b16 {%0,%1}, [%2];"
                 : "=r"(r[0]), "=r"(r[1]) : "r"(a));
}
__device__ __forceinline__ void mma_bf16(float* c, const uint32_t* a, uint32_t b0, uint32_t b1) {
    asm volatile(
        "mma.sync.aligned.m16n8k16.row.col.f32.bf16.bf16.f32 "
        "{%0,%1,%2,%3}, {%4,%5,%6,%7}, {%8,%9}, {%0,%1,%2,%3};\n"
        : "+f"(c[0]), "+f"(c[1]), "+f"(c[2]), "+f"(c[3])
        : "r"(a[0]), "r"(a[1]), "r"(a[2]), "r"(a[3]), "r"(b0), "r"(b1));
}

// ---------------------------------------------------------------------------
// block reduce (256 threads)
// ---------------------------------------------------------------------------
__device__ __forceinline__ float block_reduce_sum_256(float v, float* red)
{
    #pragma unroll
    for (int o = 16; o; o >>= 1) v += __shfl_xor_sync(0xFFFFFFFFu, v, o);
    if ((threadIdx.x & 31) == 0) red[threadIdx.x >> 5] = v;
    __syncthreads();
    float tot = 0.f;
    #pragma unroll
    for (int w = 0; w < 8; w++) tot += red[w];
    return tot;
}

// ---------------------------------------------------------------------------
// Weight prep work item (range-dispatched; W12 interleaved)
// ---------------------------------------------------------------------------
constexpr size_t WP_N1 = (size_t)3 * D_ * D_ / 4;            // Wqkv float4s
constexpr size_t WP_N2 = WP_N1 + (size_t)D_ * D_ / 4;        // + Wout
constexpr size_t WP_N3 = WP_N2 + (size_t)DFF2P_ * D_ / 4;    // + W12 interleaved
constexpr size_t WP_N4 = WP_N3 + (size_t)D_ * DFFP2_ / 2;    // + W3 (pair idx)
constexpr size_t WP_SPLIT = 1933312;                          // = 256*7552, half

__device__ __forceinline__ void weight_prep_item(size_t i,
                                                 const float* __restrict__ Wqkv,
                                                 const float* __restrict__ Wout,
                                                 const float* __restrict__ W1,
                                                 const float* __restrict__ W2,
                                                 const float* __restrict__ W3)
{
    if (i >= WP_N3) {
        size_t j = i - WP_N3;
        int n = (int)(j / (DFFP2_ / 2));
        int k2 = (int)(j - (size_t)n * (DFFP2_ / 2)) * 2;
        __nv_bfloat162 r;
        if (k2 < DFF_) {
            float2 v = *(const float2*)(W3 + (size_t)n * DFF_ + k2);
            r = __floats2bfloat162_rn(v.x, v.y);
        } else {
            r = __floats2bfloat162_rn(0.f, 0.f);
        }
        *(__nv_bfloat162*)(d_hb + HB_W3P + (size_t)n * DFFP2_ + k2) = r;
        return;
    }
    if (i >= WP_N2) {
        // W12 interleaved: dest row 2j = W1[j], 2j+1 = W2[j]; rows >= DFF2_ zero
        size_t j = i - WP_N2;
        int row = (int)(j >> 8);                // D_/4 = 256
        int c4  = (int)(j & 255);
        __nv_bfloat162* dst = (__nv_bfloat162*)(d_hb + HB_W12 + (size_t)row * D_ + c4 * 4);
        if (row < DFF2_) {
            const float* s = (row & 1) ? (W2 + (size_t)(row >> 1) * D_)
                                       : (W1 + (size_t)(row >> 1) * D_);
            float4 v = ((const float4*)s)[c4];
            dst[0] = __floats2bfloat162_rn(v.x, v.y);
            dst[1] = __floats2bfloat162_rn(v.z, v.w);
        } else {
            dst[0] = __floats2bfloat162_rn(0.f, 0.f);
            dst[1] = __floats2bfloat162_rn(0.f, 0.f);
        }
        return;
    }
    const float* src;
    __nv_bfloat162* dst;
    if (i < WP_N1) {
        src = (const float*)((const float4*)Wqkv + i);
        dst = (__nv_bfloat162*)(d_hb + HB_WQKV) + i * 2;
    } else {
        size_t j = i - WP_N1;
        src = (const float*)((const float4*)Wout + j);
        dst = (__nv_bfloat162*)(d_hb + HB_WOUT) + j * 2;
    }
    float4 v = *(const float4*)src;
    dst[0] = __floats2bfloat162_rn(v.x, v.y);
    dst[1] = __floats2bfloat162_rn(v.z, v.w);
}

// ---------------------------------------------------------------------------
// 1. Fused copy (out = x) + router scores. 4 tokens per block.
// ---------------------------------------------------------------------------
__global__ __launch_bounds__(256) void copy_router_kernel(float* __restrict__ out,
                                                          const float* __restrict__ x,
                                                          const float* __restrict__ wr)
{
    __shared__ float red[4][8];
    int tok0 = blockIdx.x * 4;
    int tid = threadIdx.x;
    float4 w = ((const float4*)wr)[tid];

    float4 v[4];
    #pragma unroll
    for (int t = 0; t < 4; t++)
        v[t] = ((const float4*)(x + (size_t)(tok0 + t) * D_))[tid];
    #pragma unroll
    for (int t = 0; t < 4; t++)
        ((float4*)(out + (size_t)(tok0 + t) * D_))[tid] = v[t];

    #pragma unroll
    for (int t = 0; t < 4; t++) {
        float dot = v[t].x * w.x + v[t].y * w.y + v[t].z * w.z + v[t].w * w.w;
        #pragma unroll
        for (int o = 16; o; o >>= 1) dot += __shfl_xor_sync(0xFFFFFFFFu, dot, o);
        if ((tid & 31) == 0) red[t][tid >> 5] = dot;
    }
    __syncthreads();
    if (tid < 4) {
        float s = 0.f;
        #pragma unroll
        for (int wv = 0; wv < 8; wv++) s += red[tid][wv];
        d_ws[OFF_SCORES + tok0 + tid] = s;
    }
}

// ---------------------------------------------------------------------------
// 2a. Top-k chunk sort (blocks 0-31) + weight-prep half 1 (blocks 32+)
// ---------------------------------------------------------------------------
__global__ __launch_bounds__(256) void topk_sort_prep_kernel(const float* __restrict__ Wqkv,
                                                             const float* __restrict__ Wout,
                                                             const float* __restrict__ W1,
                                                             const float* __restrict__ W2,
                                                             const float* __restrict__ W3)
{
    __shared__ unsigned long long key[512];

    if (blockIdx.x >= 32) {
        size_t i = (size_t)(blockIdx.x - 32) * 256 + threadIdx.x;
        if (i < WP_SPLIT)
            weight_prep_item(i, Wqkv, Wout, W1, W2, W3);
        return;
    }

    int chunk = blockIdx.x;
    int b = chunk >> 3;
    int c0 = (chunk & 7) * 512;

    for (int t = threadIdx.x; t < 512; t += 256) {
        int gi = c0 + t;
        float s = d_ws[OFF_SCORES + (size_t)b * T_ + gi];
        unsigned int u = __float_as_uint(s);
        u = (u & 0x80000000u) ? ~u : (u | 0x80000000u);
        key[t] = ((unsigned long long)u << 32) | (unsigned int)(0xFFFFFFFFu - (unsigned)gi);
    }
    __syncthreads();
    for (int k = 2; k <= 512; k <<= 1) {
        for (int j = k >> 1; j > 0; j >>= 1) {
            for (int t = threadIdx.x; t < 512; t += 256) {
                int l = t ^ j;
                if (l > t) {
                    unsigned long long a = key[t], c = key[l];
                    bool desc = ((t & k) == 0);
                    if (desc ? (a < c) : (a > c)) { key[t] = c; key[l] = a; }
                }
            }
            __syncthreads();
        }
    }
    for (int t = threadIdx.x; t < 512; t += 256)
        d_keys[(size_t)b * T_ + c0 + t] = key[t];
}

// ---------------------------------------------------------------------------
// 2b. Top-k merge (blocks 0-3) + weight-prep half 2 (blocks 4+)
// ---------------------------------------------------------------------------
__global__ __launch_bounds__(512) void topk_merge_prep_kernel(const float* __restrict__ Wqkv,
                                                              const float* __restrict__ Wout,
                                                              const float* __restrict__ W1,
                                                              const float* __restrict__ W2,
                                                              const float* __restrict__ W3)
{
    __shared__ unsigned long long key[T_];

    if (blockIdx.x >= B_) {
        size_t i = WP_SPLIT + (size_t)(blockIdx.x - B_) * 512 + threadIdx.x;
        if (i < WP_N4)
            weight_prep_item(i, Wqkv, Wout, W1, W2, W3);
        return;
    }

    int b = blockIdx.x;
    for (int t = threadIdx.x; t < T_; t += 512)
        key[t] = d_keys[(size_t)b * T_ + t];
    __syncthreads();

    #pragma unroll
    for (int r = 0; r < 3; r++) {
        int pairs = 4 >> r;
        int stride = 1024 << r;
        int half = 512 << r;
        for (int e = threadIdx.x; e < pairs * 512; e += 512) {
            int p = e >> 9, i = e & 511;
            int base = p * stride;
            unsigned long long a = key[base + i];
            unsigned long long bb = key[base + half + 511 - i];
            if (bb > a) key[base + i] = bb;
        }
        __syncthreads();
        for (int j = 256; j > 0; j >>= 1) {
            for (int e = threadIdx.x; e < pairs * 256; e += 512) {
                int p = e >> 8, q = e & 255;
                int i = ((q & ~(j - 1)) << 1) | (q & (j - 1));
                int base = p * stride;
                unsigned long long a = key[base + i], c = key[base + i + j];
                if (a < c) { key[base + i] = c; key[base + i + j] = a; }
            }
            __syncthreads();
        }
    }
    for (int t = threadIdx.x; t < CAP_; t += 512)
        d_idx[b * CAP_ + t] = (int)(0xFFFFFFFFu - (unsigned int)(key[t] & 0xFFFFFFFFu));
}

// ---------------------------------------------------------------------------
// 3. Gather + RMSNorm (writes XSEL fp32 + H bf16)
// ---------------------------------------------------------------------------
__global__ __launch_bounds__(256) void gather_rmsnorm_kernel(const float* __restrict__ x,
                                                             const float* __restrict__ g)
{
    __shared__ float red[8];
    int row = blockIdx.x;
    int b = row >> 9;
    int t = d_idx[row];
    int tid = threadIdx.x;
    float4 v = ((const float4*)(x + ((size_t)b * T_ + t) * D_))[tid];
    float ss = v.x*v.x + v.y*v.y + v.z*v.z + v.w*v.w;
    float tot = block_reduce_sum_256(ss, red);
    float rinv = rsqrtf(tot * (1.f / D_) + 1e-6f);
    float4 gv = ((const float4*)g)[tid];
    ((float4*)(d_ws + OFF_XSEL + (size_t)row * D_))[tid] = v;
    __nv_bfloat162* hb = (__nv_bfloat162*)(d_hb + HB_H + (size_t)row * D_);
    hb[tid * 2]     = __floats2bfloat162_rn(v.x * rinv * gv.x, v.y * rinv * gv.y);
    hb[tid * 2 + 1] = __floats2bfloat162_rn(v.z * rinv * gv.z, v.w * rinv * gv.w);
}

// ---------------------------------------------------------------------------
// 4. RMSNorm y1 -> H2b
// ---------------------------------------------------------------------------
__global__ __launch_bounds__(256) void rmsnorm2_kernel(const float* __restrict__ g)
{
    __shared__ float red[8];
    int row = blockIdx.x;
    int tid = threadIdx.x;
    float4 v = ((const float4*)(d_ws + OFF_Y1 + (size_t)row * D_))[tid];
    float ss = v.x*v.x + v.y*v.y + v.z*v.z + v.w*v.w;
    float tot = block_reduce_sum_256(ss, red);
    float rinv = rsqrtf(tot * (1.f / D_) + 1e-6f);
    float4 gv = ((const float4*)g)[tid];
    __nv_bfloat162* hb = (__nv_bfloat162*)(d_hb + HB_H2 + (size_t)row * D_);
    hb[tid * 2]     = __floats2bfloat162_rn(v.x * rinv * gv.x, v.y * rinv * gv.y);
    hb[tid * 2 + 1] = __floats2bfloat162_rn(v.z * rinv * gv.z, v.w * rinv * gv.w);
}

// ---------------------------------------------------------------------------
// 5. BF16 mma.sync GEMM (NT) — round-9 exact mainloop.
//    mode 0: fp32 out (+ADD). mode 1: bf16 out.
//    mode 2: swiglu bf16 out (interleaved cols -> silu(even)*odd at c/2).
//    mode 3: fp32 out, rows scattered to out via d_idx.
// ---------------------------------------------------------------------------
#define GBK2 32
#define BPITCH 40
#define G_NST 3
constexpr int G_STAGE_HALVES = 2 * 128 * BPITCH;
constexpr int G_SMEM_BYTES   = G_NST * G_STAGE_HALVES * 2;   // 61440

__global__ __launch_bounds__(256, 2) void bf16_gemm_nt(const __nv_bfloat16* __restrict__ A,
                                                       const __nv_bfloat16* __restrict__ Bw,
                                                       void* __restrict__ Cv,
                                                       const float* __restrict__ ADD,
                                                       int M, int N, int K, int ldc,
                                                       int mode)
{
    extern __shared__ __nv_bfloat16 gs[];

    const int tid  = threadIdx.x;
    const int lane = tid & 31, warp = tid >> 5;
    const int g    = lane >> 2, tg = lane & 3;
    const int wm   = warp >> 2;
    const int wn   = warp & 3;
    const int row0 = blockIdx.y * 128;
    const int col0 = blockIdx.x * 128;
    const int nk   = K / GBK2;

    float acc[4][4][4];
    #pragma unroll
    for (int i = 0; i < 4; i++)
        #pragma unroll
        for (int j = 0; j < 4; j++)
            #pragma unroll
            for (int r = 0; r < 4; r++) acc[i][j][r] = 0.f;

    auto issue = [&](int s, int ki) {
        __nv_bfloat16* As = gs + s * G_STAGE_HALVES;
        __nv_bfloat16* Bs = As + 128 * BPITCH;
        int k0 = ki * GBK2;
        #pragma unroll
        for (int i = 0; i < 2; i++) {
            int c = tid + 256 * i;
            int r = c >> 2, off = (c & 3) * 8;
            cp_async16((uint32_t)__cvta_generic_to_shared(&As[r * BPITCH + off]),
                       A + (size_t)(row0 + r) * K + k0 + off, true);
            cp_async16((uint32_t)__cvta_generic_to_shared(&Bs[r * BPITCH + off]),
                       Bw + (size_t)(col0 + r) * K + k0 + off, (col0 + r) < N);
        }
        asm volatile("cp.async.commit_group;\n");
    };

    issue(0, 0);
    issue(1, 1);
    issue(2, 2);

    for (int i = 0; i < nk; i++) {
        int s = i - (i / G_NST) * G_NST;
        int issued = (i + G_NST < nk) ? (i + G_NST) : nk;
        int pend = issued - i - 1;
        if (pend >= 2)      asm volatile("cp.async.wait_group 2;\n");
        else if (pend == 1) asm volatile("cp.async.wait_group 1;\n");
        else                asm volatile("cp.async.wait_group 0;\n");
        __syncthreads();

        const __nv_bfloat16* As = gs + s * G_STAGE_HALVES;
        const __nv_bfloat16* Bs = As + 128 * BPITCH;

        #pragma unroll
        for (int kk = 0; kk < GBK2; kk += 16) {
            uint32_t af[4][4];
            #pragma unroll
            for (int mt = 0; mt < 4; mt++)
                ldsm_x4(af[mt], &As[(wm * 64 + mt * 16 + (lane & 15)) * BPITCH
                                    + kk + ((lane >> 4) << 3)]);
            #pragma unroll
            for (int pb = 0; pb < 2; pb++) {
                uint32_t bq[4];
                ldsm_x4(bq, &Bs[(wn * 32 + pb * 16 + (lane & 7) + ((lane >> 3) & 1) * 8) * BPITCH
                                + kk + ((lane >> 4) << 3)]);
                #pragma unroll
                for (int mt = 0; mt < 4; mt++) {
                    mma_bf16(acc[mt][pb * 2],     af[mt], bq[0], bq[2]);
                    mma_bf16(acc[mt][pb * 2 + 1], af[mt], bq[1], bq[3]);
                }
            }
        }
        __syncthreads();

        if (i + G_NST < nk) issue(s, i + G_NST);
    }

    if (mode == 2) {
        // swiglu: silu(even col) * odd col -> U at column c/2, pitch ldc
        __nv_bfloat16* C = (__nv_bfloat16*)Cv;
        #pragma unroll
        for (int mt = 0; mt < 4; mt++) {
            int r1 = row0 + wm * 64 + mt * 16 + g;
            int r2 = r1 + 8;
            #pragma unroll
            for (int nt = 0; nt < 4; nt++) {
                int ch = (col0 >> 1) + wn * 16 + nt * 4 + tg;
                float a0 = acc[mt][nt][0], c0 = acc[mt][nt][1];
                float a1 = acc[mt][nt][2], c1 = acc[mt][nt][3];
                C[(size_t)r1 * ldc + ch] = __float2bfloat16(a0 / (1.f + __expf(-a0)) * c0);
                C[(size_t)r2 * ldc + ch] = __float2bfloat16(a1 / (1.f + __expf(-a1)) * c1);
            }
        }
        return;
    }

    #pragma unroll
    for (int mt = 0; mt < 4; mt++) {
        int r1 = row0 + wm * 64 + mt * 16 + g;
        int r2 = r1 + 8;
        size_t or1 = (size_t)r1, or2 = (size_t)r2;
        if (mode == 3) {
            or1 = (size_t)((r1 >> 9) * T_ + d_idx[r1]);
            or2 = (size_t)((r2 >> 9) * T_ + d_idx[r2]);
        }
        #pragma unroll
        for (int nt = 0; nt < 4; nt++) {
            int c = col0 + wn * 32 + nt * 8 + 2 * tg;
            if (c < N) {
                float2 v0 = make_float2(acc[mt][nt][0], acc[mt][nt][1]);
                float2 v1 = make_float2(acc[mt][nt][2], acc[mt][nt][3]);
                if (ADD) {
                    float2 a0 = *(const float2*)&ADD[(size_t)r1 * ldc + c];
                    float2 a1 = *(const float2*)&ADD[(size_t)r2 * ldc + c];
                    v0.x += a0.x; v0.y += a0.y;
                    v1.x += a1.x; v1.y += a1.y;
                }
                if (mode == 1) {
                    __nv_bfloat16* C = (__nv_bfloat16*)Cv;
                    *(__nv_bfloat162*)&C[(size_t)r1 * ldc + c] = __floats2bfloat162_rn(v0.x, v0.y);
                    *(__nv_bfloat162*)&C[(size_t)r2 * ldc + c] = __floats2bfloat162_rn(v1.x, v1.y);
                } else {
                    float* C = (float*)Cv;
                    *(float2*)&C[or1 * ldc + c] = v0;
                    *(float2*)&C[or2 * ldc + c] = v1;
                }
            }
        }
    }
}

// ---------------------------------------------------------------------------
// 5b. BM=64 GEMM variant (Wout, W3-down). Unchanged from round 16.
// ---------------------------------------------------------------------------
constexpr int G64_STAGE_HALVES = (64 + 128) * BPITCH;
constexpr int G64_SMEM_BYTES   = G_NST * G64_STAGE_HALVES * 2;

__global__ __launch_bounds__(256, 2) void bf16_gemm_nt_m64(const __nv_bfloat16* __restrict__ A,
                                                           const __nv_bfloat16* __restrict__ Bw,
                                                           void* __restrict__ Cv,
                                                           const float* __restrict__ ADD,
                                                           int M, int N, int K, int ldc,
                                                           int mode)
{
    extern __shared__ __nv_bfloat16 gs[];

    const int tid  = threadIdx.x;
    const int lane = tid & 31, warp = tid >> 5;
    const int g    = lane >> 2, tg = lane & 3;
    const int wn   = warp;
    const int row0 = blockIdx.y * 64;
    const int col0 = blockIdx.x * 128;
    const int nk   = K / GBK2;

    float acc[4][2][4];
    #pragma unroll
    for (int i = 0; i < 4; i++)
        #pragma unroll
        for (int j = 0; j < 2; j++)
            #pragma unroll
            for (int r = 0; r < 4; r++) acc[i][j][r] = 0.f;

    auto issue = [&](int s, int ki) {
        __nv_bfloat16* As = gs + s * G64_STAGE_HALVES;
        __nv_bfloat16* Bs = As + 64 * BPITCH;
        int k0 = ki * GBK2;
        #pragma unroll
        for (int i = 0; i < 3; i++) {
            int c = tid + 256 * i;
            if (c < 256) {
                int r = c >> 2, off = (c & 3) * 8;
                cp_async16((uint32_t)__cvta_generic_to_shared(&As[r * BPITCH + off]),
                           A + (size_t)(row0 + r) * K + k0 + off, true);
            } else {
                int j = c - 256;
                int r = j >> 2, off = (j & 3) * 8;
                cp_async16((uint32_t)__cvta_generic_to_shared(&Bs[r * BPITCH + off]),
                           Bw + (size_t)(col0 + r) * K + k0 + off, (col0 + r) < N);
            }
        }
        asm volatile("cp.async.commit_group;\n");
    };

    issue(0, 0);
    issue(1, 1);
    issue(2, 2);

    for (int i = 0; i < nk; i++) {
        int s = i - (i / G_NST) * G_NST;
        int issued = (i + G_NST < nk) ? (i + G_NST) : nk;
        int pend = issued - i - 1;
        if (pend >= 2)      asm volatile("cp.async.wait_group 2;\n");
        else if (pend == 1) asm volatile("cp.async.wait_group 1;\n");
        else                asm volatile("cp.async.wait_group 0;\n");
        __syncthreads();

        const __nv_bfloat16* As = gs + s * G64_STAGE_HALVES;
        const __nv_bfloat16* Bs = As + 64 * BPITCH;

        #pragma unroll
        for (int kk = 0; kk < GBK2; kk += 16) {
            uint32_t af[4][4];
            #pragma unroll
            for (int mt = 0; mt < 4; mt++)
                ldsm_x4(af[mt], &As[(mt * 16 + (lane & 15)) * BPITCH
                                    + kk + ((lane >> 4) << 3)]);
            uint32_t bq[4];
            ldsm_x4(bq, &Bs[(wn * 16 + (lane & 7) + ((lane >> 3) & 1) * 8) * BPITCH
                            + kk + ((lane >> 4) << 3)]);
            #pragma unroll
            for (int mt = 0; mt < 4; mt++) {
                mma_bf16(acc[mt][0], af[mt], bq[0], bq[2]);
                mma_bf16(acc[mt][1], af[mt], bq[1], bq[3]);
            }
        }
        __syncthreads();

        if (i + G_NST < nk) issue(s, i + G_NST);
    }

    #pragma unroll
    for (int mt = 0; mt < 4; mt++) {
        int r1 = row0 + mt * 16 + g;
        int r2 = r1 + 8;
        size_t or1 = (size_t)r1, or2 = (size_t)r2;
        if (mode == 3) {
            or1 = (size_t)((r1 >> 9) * T_ + d_idx[r1]);
            or2 = (size_t)((r2 >> 9) * T_ + d_idx[r2]);
        }
        #pragma unroll
        for (int nt = 0; nt < 2; nt++) {
            int c = col0 + wn * 16 + nt * 8 + 2 * tg;
            if (c < N) {
                float2 v0 = make_float2(acc[mt][nt][0], acc[mt][nt][1]);
                float2 v1 = make_float2(acc[mt][nt][2], acc[mt][nt][3]);
                if (ADD) {
                    float2 a0 = *(const float2*)&ADD[(size_t)r1 * ldc + c];
                    float2 a1 = *(const float2*)&ADD[(size_t)r2 * ldc + c];
                    v0.x += a0.x; v0.y += a0.y;
                    v1.x += a1.x; v1.y += a1.y;
                }
                if (mode == 1) {
                    __nv_bfloat16* C = (__nv_bfloat16*)Cv;
                    *(__nv_bfloat162*)&C[(size_t)r1 * ldc + c] = __floats2bfloat162_rn(v0.x, v0.y);
                    *(__nv_bfloat162*)&C[(size_t)r2 * ldc + c] = __floats2bfloat162_rn(v1.x, v1.y);
                } else {
                    float* C = (float*)Cv;
                    *(float2*)&C[or1 * ldc + c] = v0;
                    *(float2*)&C[or2 * ldc + c] = v1;
                }
            }
        }
    }
}

// ---------------------------------------------------------------------------
// 6. Fused flash attention (bf16 mma.sync, validated round 4)
// ---------------------------------------------------------------------------
#define AP 72
#define SP 68
constexpr int FA_SMEM_BYTES = (4 * 64 * AP) * 2 + (64 * SP + 3 * 64) * 4;

__global__ __launch_bounds__(128) void flash_attn_kernel()
{
    extern __shared__ char fsm_raw[];
    __nv_bfloat16* Qs = (__nv_bfloat16*)fsm_raw;
    __nv_bfloat16* Ks = Qs + 64 * AP;
    __nv_bfloat16* Vs = Ks + 64 * AP;
    __nv_bfloat16* Pb = Vs + 64 * AP;
    float* Sf   = (float*)(Pb + 64 * AP);
    float* smM  = Sf + 64 * SP;
    float* smL  = smM + 64;
    float* smSc = smL + 64;

    const int bh = blockIdx.x;
    const int it = 7 - blockIdx.y;
    const int b  = bh >> 4, h = bh & 15;
    const int tid = threadIdx.x;
    const int lane = tid & 31, w = tid >> 5;
    const int g = lane >> 2, tg = lane & 3;
    const int m0 = w * 16;

    const __nv_bfloat16* qkv = d_hb + HB_QKV;
    const int tokQ0 = b * CAP_ + it * 64;

    #pragma unroll
    for (int i = 0; i < 4; i++) {
        int c = tid + 128 * i;
        int r = c >> 3, off = (c & 7) * 8;
        cp_async16((uint32_t)__cvta_generic_to_shared(&Qs[r * AP + off]),
                   qkv + (size_t)(tokQ0 + r) * (3 * D_) + h * 64 + off, true);
    }
    asm volatile("cp.async.commit_group;\n");

    if (tid < 64) { smM[tid] = -1e30f; smL[tid] = 0.f; }

    float acc[8][4];
    #pragma unroll
    for (int nt = 0; nt < 8; nt++)
        #pragma unroll
        for (int r = 0; r < 4; r++) acc[nt][r] = 0.f;

    for (int jt = 0; jt <= it; jt++) {
        const int tokK0 = b * CAP_ + jt * 64;
        #pragma unroll
        for (int i = 0; i < 4; i++) {
            int c = tid + 128 * i;
            int r = c >> 3, off = (c & 7) * 8;
            cp_async16((uint32_t)__cvta_generic_to_shared(&Ks[r * AP + off]),
                       qkv + (size_t)(tokK0 + r) * (3 * D_) + D_ + h * 64 + off, true);
            cp_async16((uint32_t)__cvta_generic_to_shared(&Vs[r * AP + off]),
                       qkv + (size_t)(tokK0 + r) * (3 * D_) + 2 * D_ + h * 64 + off, true);
        }
        asm volatile("cp.async.commit_group;\n");
        asm volatile("cp.async.wait_group 0;\n");
        __syncthreads();

        float sacc[8][4];
        #pragma unroll
        for (int nt = 0; nt < 8; nt++)
            #pragma unroll
            for (int r = 0; r < 4; r++) sacc[nt][r] = 0.f;

        #pragma unroll
        for (int kk = 0; kk < 64; kk += 16) {
            uint32_t a[4];
            ldsm_x4(a, &Qs[(m0 + (lane & 15)) * AP + kk + ((lane >> 4) << 3)]);
            #pragma unroll
            for (int nt = 0; nt < 8; nt++) {
                uint32_t bb[2];
                ldsm_x2(bb, &Ks[(nt * 8 + (lane & 7)) * AP + kk + (((lane >> 3) & 1) << 3)]);
                mma_bf16(sacc[nt], a, bb[0], bb[1]);
            }
        }

        const bool diag = (jt == it);
        const int r0l = m0 + g, r1l = r0l + 8;
        #pragma unroll
        for (int nt = 0; nt < 8; nt++) {
            int c0 = nt * 8 + 2 * tg, c1 = c0 + 1;
            float s00 = sacc[nt][0] * 0.125f, s01 = sacc[nt][1] * 0.125f;
            float s10 = sacc[nt][2] * 0.125f, s11 = sacc[nt][3] * 0.125f;
            if (diag) {
                if (c0 > r0l) s00 = -1e30f;
                if (c1 > r0l) s01 = -1e30f;
                if (c0 > r1l) s10 = -1e30f;
                if (c1 > r1l) s11 = -1e30f;
            }
            Sf[r0l * SP + c0] = s00; Sf[r0l * SP + c1] = s01;
            Sf[r1l * SP + c0] = s10; Sf[r1l * SP + c1] = s11;
        }
        __syncwarp();

        {
            int row = m0 + (lane >> 1);
            int cbase = (lane & 1) * 32;
            float* srow = &Sf[row * SP + cbase];
            __nv_bfloat16* prow = &Pb[row * AP + cbase];
            float mloc = -1e30f;
            #pragma unroll
            for (int c = 0; c < 32; c++) mloc = fmaxf(mloc, srow[c]);
            mloc = fmaxf(mloc, __shfl_xor_sync(0xFFFFFFFFu, mloc, 1));
            float mOld = smM[row];
            float mNew = fmaxf(mOld, mloc);
            float sc = __expf(mOld - mNew);
            float s = 0.f;
            #pragma unroll
            for (int c = 0; c < 32; c++) {
                float e = __expf(srow[c] - mNew);
                prow[c] = __float2bfloat16(e);
                s += e;
            }
            s += __shfl_xor_sync(0xFFFFFFFFu, s, 1);
            if ((lane & 1) == 0) {
                smM[row]  = mNew;
                smL[row]  = smL[row] * sc + s;
                smSc[row] = sc;
            }
        }
        __syncwarp();

        {
            float sc0 = smSc[m0 + g], sc1 = smSc[m0 + g + 8];
            #pragma unroll
            for (int nt = 0; nt < 8; nt++) {
                acc[nt][0] *= sc0; acc[nt][1] *= sc0;
                acc[nt][2] *= sc1; acc[nt][3] *= sc1;
            }
        }
        #pragma unroll
        for (int kk = 0; kk < 64; kk += 16) {
            uint32_t a[4];
            ldsm_x4(a, &Pb[(m0 + (lane & 15)) * AP + kk + ((lane >> 4) << 3)]);
            #pragma unroll
            for (int nt = 0; nt < 8; nt++) {
                uint32_t bb[2];
                ldsm_x2t(bb, &Vs[(kk + (lane & 15)) * AP + nt * 8]);
                mma_bf16(acc[nt], a, bb[0], bb[1]);
            }
        }
        __syncthreads();
    }

    float inv0 = 1.f / smL[m0 + g];
    float inv1 = 1.f / smL[m0 + g + 8];
    __nv_bfloat16* O = d_hb + HB_ATTN;
    int tok0 = tokQ0 + m0 + g;
    #pragma unroll
    for (int nt = 0; nt < 8; nt++) {
        int c = h * 64 + nt * 8 + 2 * tg;
        *(__nv_bfloat162*)&O[(size_t)tok0 * D_ + c] =
            __floats2bfloat162_rn(acc[nt][0] * inv0, acc[nt][1] * inv0);
        *(__nv_bfloat162*)&O[(size_t)(tok0 + 8) * D_ + c] =
            __floats2bfloat162_rn(acc[nt][2] * inv1, acc[nt][3] * inv1);
    }
}

// ---------------------------------------------------------------------------
// Launcher
// ---------------------------------------------------------------------------
extern "C" void kernel_launch(void* const* d_in, const int* in_sizes, int n_in,
                              void* d_out, int out_size)
{
    const float* x    = (const float*)d_in[0];
    const float* wr   = (const float*)d_in[1];
    const float* Wqkv = (const float*)d_in[2];
    const float* Wout = (const float*)d_in[3];
    const float* g1   = (const float*)d_in[4];
    const float* g2   = (const float*)d_in[5];
    const float* W1   = (const float*)d_in[6];
    const float* W2   = (const float*)d_in[7];
    const float* W3   = (const float*)d_in[8];
    float* out = (float*)d_out;

    float* ws = nullptr;
    __nv_bfloat16* hb = nullptr;
    cudaGetSymbolAddress((void**)&ws, d_ws);
    cudaGetSymbolAddress((void**)&hb, d_hb);
    cudaFuncSetAttribute(flash_attn_kernel,
                         cudaFuncAttributeMaxDynamicSharedMemorySize, FA_SMEM_BYTES);
    cudaFuncSetAttribute(bf16_gemm_nt,
                         cudaFuncAttributeMaxDynamicSharedMemorySize, G_SMEM_BYTES);
    cudaFuncSetAttribute(bf16_gemm_nt_m64,
                         cudaFuncAttributeMaxDynamicSharedMemorySize, G64_SMEM_BYTES);

    auto gemm = [&](const __nv_bfloat16* A, const __nv_bfloat16* Bw, void* C,
                    const float* ADD, int M, int N, int K, int ldc, int mode) {
        dim3 grid((N + 127) / 128, M / 128);
        bf16_gemm_nt<<<grid, 256, G_SMEM_BYTES>>>(A, Bw, C, ADD, M, N, K, ldc, mode);
    };
    auto gemm64 = [&](const __nv_bfloat16* A, const __nv_bfloat16* Bw, void* C,
                      const float* ADD, int M, int N, int K, int ldc, int mode) {
        dim3 grid((N + 127) / 128, M / 64);
        bf16_gemm_nt_m64<<<grid, 256, G64_SMEM_BYTES>>>(A, Bw, C, ADD, M, N, K, ldc, mode);
    };

    // fused copy+router; overlapped top-k + weight-prep
    copy_router_kernel<<<B_ * T_ / 4, 256>>>(out, x, wr);
    topk_sort_prep_kernel<<<32 + (int)(WP_SPLIT / 256), 256>>>(Wqkv, Wout, W1, W2, W3);
    topk_merge_prep_kernel<<<B_ + (int)((WP_N4 - WP_SPLIT + 511) / 512), 512>>>(Wqkv, Wout, W1, W2, W3);

    gather_rmsnorm_kernel<<<M_, 256>>>(x, g1);

    // QKV projection -> bf16
    gemm(hb + HB_H, hb + HB_WQKV, hb + HB_QKV, nullptr, M_, 3 * D_, D_, 3 * D_, 1);

    flash_attn_kernel<<<dim3(B_ * H_, 8), 128, FA_SMEM_BYTES>>>();

    // out projection + residual (XSEL) -> fp32 Y1 (BM=64 variant)
    gemm64(hb + HB_ATTN, hb + HB_WOUT, ws + OFF_Y1, ws + OFF_XSEL, M_, D_, D_, D_, 0);

    rmsnorm2_kernel<<<M_, 256>>>(g2);

    // fused FFN up (interleaved W1|W2) + swiglu epilogue -> bf16 U directly
    gemm(hb + HB_H2, hb + HB_W12, hb + HB_U, nullptr, M_, DFF2P_, D_, DFFP2_, 2);

    // FFN down + residual, scattered into out (BM=64 variant)
    gemm64(hb + HB_U, hb + HB_W3P, out, ws + OFF_Y1, M_, D_, DFFP2_, D_, 3);
}